// round 1
// baseline (speedup 1.0000x reference)
#include <cuda_runtime.h>
#include <cuda_bf16.h>

#define T_LEN 2048
#define C_DIM 2048
#define H_NUM 16
#define N_DIM 128
#define KVH_NUM 4
#define HN_DIM 2048
#define KVN_DIM 512

// ---------------- scratch (static device globals; no runtime alloc) ----------------
__device__ float g_xm[T_LEN * C_DIM];
__device__ float g_xr[T_LEN * HN_DIM];
__device__ float g_xk[T_LEN * KVN_DIM];
__device__ float g_xv[T_LEN * KVN_DIM];
__device__ float g_tw[T_LEN * 160];
__device__ float g_ta[T_LEN * 96];
__device__ float g_tv[T_LEN * 64];
__device__ float g_tk[T_LEN * 64];
__device__ float g_tg[T_LEN * 160];
__device__ float g_wfull[T_LEN * HN_DIM];
__device__ float g_afull[T_LEN * HN_DIM];
__device__ float g_gfull[T_LEN * HN_DIM];
__device__ float g_vmix[T_LEN * KVN_DIM];
__device__ float g_kmix[T_LEN * KVN_DIM];
__device__ float g_rr[T_LEN * HN_DIM];
__device__ float g_kf[T_LEN * KVN_DIM];
__device__ float g_vf[T_LEN * KVN_DIM];
__device__ float g_kk[T_LEN * KVN_DIM];
__device__ float g_wd[T_LEN * HN_DIM];
__device__ float g_bb[T_LEN * HN_DIM];
__device__ float g_coef[T_LEN * H_NUM];
__device__ float g_y[T_LEN * HN_DIM];
__device__ float g_yg[T_LEN * HN_DIM];

// ---------------- helpers ----------------
__device__ __forceinline__ float sigmoidf_(float x) {
    return 1.0f / (1.0f + expf(-x));
}

// block of 128 threads; red must be shared float[4]
__device__ __forceinline__ float blockReduceSum128(float v, float* red) {
#pragma unroll
    for (int m = 16; m > 0; m >>= 1) v += __shfl_xor_sync(0xffffffffu, v, m);
    __syncthreads();  // protect red from any prior use
    if ((threadIdx.x & 31) == 0) red[threadIdx.x >> 5] = v;
    __syncthreads();
    return red[0] + red[1] + red[2] + red[3];
}

// ---------------- elementwise: xm = x * mask ----------------
__global__ void maskmul_kernel(const float* __restrict__ x, const float* __restrict__ mask,
                               float* __restrict__ xm, int n) {
    int i = blockIdx.x * blockDim.x + threadIdx.x;
    if (i < n) xm[i] = x[i] * mask[i >> 11];  // C_DIM = 2048
}

// ---------------- activations on small LoRA mids ----------------
__global__ void act_kernel(float* __restrict__ tw, float* __restrict__ tg, int n) {
    int i = blockIdx.x * blockDim.x + threadIdx.x;
    if (i < n) {
        tw[i] = tanhf(tw[i]);
        tg[i] = sigmoidf_(tg[i]);
    }
}

// ---------------- SGEMM: C[M,N] = A[M,K] @ B[K,N], fp32, row-major ----------------
// Requires: M % 128 == 0, K % 8 == 0, N % 4 == 0 (true for all calls here).
__global__ __launch_bounds__(256) void sgemm_kernel(const float* __restrict__ A,
                                                    const float* __restrict__ B,
                                                    float* __restrict__ C,
                                                    int M, int N, int K) {
    __shared__ float As[8][128];
    __shared__ float Bs[8][128];
    const int tid = threadIdx.x;
    const int bm = blockIdx.y * 128;
    const int bn = blockIdx.x * 128;
    const int tx = tid & 15;
    const int ty = tid >> 4;

    const int arow = tid >> 1;
    const int acol = (tid & 1) * 4;
    const int brow = tid >> 5;
    const int bcol = (tid & 31) * 4;

    float acc[8][8];
#pragma unroll
    for (int i = 0; i < 8; i++)
#pragma unroll
        for (int j = 0; j < 8; j++) acc[i][j] = 0.0f;

    for (int k0 = 0; k0 < K; k0 += 8) {
        float4 av = *(const float4*)(A + (bm + arow) * K + k0 + acol);
        float4 bv;
        int gcol = bn + bcol;
        if (gcol < N)
            bv = *(const float4*)(B + (k0 + brow) * N + gcol);
        else
            bv = make_float4(0.f, 0.f, 0.f, 0.f);

        __syncthreads();  // previous iteration's compute done
        As[acol + 0][arow] = av.x;
        As[acol + 1][arow] = av.y;
        As[acol + 2][arow] = av.z;
        As[acol + 3][arow] = av.w;
        *(float4*)&Bs[brow][bcol] = bv;
        __syncthreads();

#pragma unroll
        for (int kk = 0; kk < 8; kk++) {
            float4 a0v = *(const float4*)&As[kk][ty * 8];
            float4 a1v = *(const float4*)&As[kk][ty * 8 + 4];
            float4 b0v = *(const float4*)&Bs[kk][tx * 8];
            float4 b1v = *(const float4*)&Bs[kk][tx * 8 + 4];
            float a[8] = {a0v.x, a0v.y, a0v.z, a0v.w, a1v.x, a1v.y, a1v.z, a1v.w};
            float b[8] = {b0v.x, b0v.y, b0v.z, b0v.w, b1v.x, b1v.y, b1v.z, b1v.w};
#pragma unroll
            for (int i = 0; i < 8; i++)
#pragma unroll
                for (int j = 0; j < 8; j++) acc[i][j] = fmaf(a[i], b[j], acc[i][j]);
        }
    }

#pragma unroll
    for (int i = 0; i < 8; i++) {
        int r = bm + ty * 8 + i;
#pragma unroll
        for (int j = 0; j < 8; j++) {
            int c = bn + tx * 8 + j;
            if (c < N) C[r * N + c] = acc[i][j];
        }
    }
}

// ---------------- postprocess per (t, kvh): k-norm/rope/mix, v-mix, kk ----------------
__global__ void pp_kv_kernel(const float* __restrict__ xk, const float* __restrict__ xv,
                             const float* __restrict__ kmix, const float* __restrict__ vmix,
                             const float* __restrict__ k_first, const float* __restrict__ v_first,
                             const float* __restrict__ k0, const float* __restrict__ v0,
                             const float* __restrict__ knw, const float* __restrict__ cosb,
                             const float* __restrict__ sinb,
                             float* __restrict__ kf, float* __restrict__ vfout,
                             float* __restrict__ kkout) {
    int t = blockIdx.x, kvh = blockIdx.y, n = threadIdx.x;
    int idx = t * KVN_DIM + kvh * 128 + n;
    __shared__ float shk[128];
    __shared__ float red[4];

    float k = xk[idx];
    float ss = blockReduceSum128(k * k, red);
    float kn = knw[n] * k * rsqrtf(ss * (1.0f / 128.0f) + 1e-6f);
    shk[n] = kn;
    __syncthreads();
    float rh = (n < 64) ? -shk[n + 64] : shk[n - 64];
    float c = cosb[t * 128 + n], s = sinb[t * 128 + n];
    float kr = fmaf(kn, c, rh * s);

    float kfv = kr + (k_first[idx] - kr) * sigmoidf_(k0[kvh * 128 + n] + kmix[idx]);
    float vv = xv[idx];
    float vfv = vv + (v_first[idx] - vv) * sigmoidf_(v0[kvh * 128 + n] + vmix[idx]);

    float nrm2 = blockReduceSum128(kfv * kfv, red);
    float denom = fmaxf(sqrtf(nrm2), 1e-12f);

    kf[idx] = kfv;
    vfout[idx] = vfv;
    kkout[idx] = kfv / denom;
}

// ---------------- postprocess per (t, h): r norm/rope, wdec, bb, bonus coeff ----------------
__global__ void pp_h_kernel(const float* __restrict__ xr, const float* __restrict__ wfull,
                            const float* __restrict__ afull,
                            const float* __restrict__ w0, const float* __restrict__ a0,
                            const float* __restrict__ kkbuf, const float* __restrict__ kfbuf,
                            const float* __restrict__ rnw, const float* __restrict__ cosb,
                            const float* __restrict__ sinb, const float* __restrict__ r_k,
                            float* __restrict__ rout, float* __restrict__ wdout,
                            float* __restrict__ bbout, float* __restrict__ coef) {
    int t = blockIdx.x, h = blockIdx.y, n = threadIdx.x;
    int hn = h * 128 + n;
    int idx = t * HN_DIM + hn;
    __shared__ float shr[128];
    __shared__ float red[4];

    float r = xr[idx];
    float ss = blockReduceSum128(r * r, red);
    float rn = rnw[n] * r * rsqrtf(ss * (1.0f / 128.0f) + 1e-6f);
    shr[n] = rn;
    __syncthreads();
    float rh = (n < 64) ? -shr[n + 64] : shr[n - 64];
    float c = cosb[t * 128 + n], s = sinb[t * 128 + n];
    float rr = fmaf(rn, c, rh * s);
    rout[idx] = rr;

    // w = -softplus(-(w0 + wfull)) - 0.5 ; wdec = exp(-exp(w))
    float z = w0[hn] + wfull[idx];
    float u = -z;
    float sp = fmaxf(u, 0.0f) + log1pf(expf(-fabsf(u)));  // softplus(-z), stable
    float w = -sp - 0.5f;
    wdout[idx] = expf(-expf(w));

    float a = sigmoidf_(a0[hn] + afull[idx]);
    int kvidx = t * KVN_DIM + (h >> 2) * 128 + n;
    bbout[idx] = kkbuf[kvidx] * a;

    float cp = rr * kfbuf[kvidx] * r_k[hn];
    float cs = blockReduceSum128(cp, red);
    if (n == 0) coef[t * H_NUM + h] = cs;
}

// ---------------- the sequential scan ----------------
// grid (H=16, RG=8), 128 threads: 16 rows x 8 j-chunks of 16. Row-independent recurrence.
__global__ __launch_bounds__(128) void scan_kernel(const float* __restrict__ wdec,
                                                   const float* __restrict__ bb,
                                                   const float* __restrict__ kk,
                                                   const float* __restrict__ kf,
                                                   const float* __restrict__ rr,
                                                   const float* __restrict__ vf,
                                                   float* __restrict__ y) {
    const int h = blockIdx.x;
    const int rg = blockIdx.y;
    const int tid = threadIdx.x;
    const int rl = tid >> 3;   // local row 0..15
    const int jc = tid & 7;    // j-chunk 0..7
    const int row = rg * 16 + rl;
    const int kvh = h >> 2;
    const int j0 = jc * 16;

    __shared__ float sw[128], sb[128], sk[128], skf[128], sr[128], sv[16];

    float S[16];
#pragma unroll
    for (int i = 0; i < 16; i++) S[i] = 0.0f;

    // prefetch t = 0
    int bH = h * 128;
    int bKV = kvh * 128;
    float pw = wdec[bH + tid];
    float pb = bb[bH + tid];
    float pr = rr[bH + tid];
    float pk = kk[bKV + tid];
    float pkf = kf[bKV + tid];
    float pv = (tid < 16) ? vf[bKV + rg * 16 + tid] : 0.0f;

    for (int t = 0; t < T_LEN; t++) {
        sw[tid] = pw;
        sb[tid] = pb;
        sr[tid] = pr;
        sk[tid] = pk;
        skf[tid] = pkf;
        if (tid < 16) sv[tid] = pv;
        __syncthreads();

        if (t + 1 < T_LEN) {  // prefetch next step, overlapped with compute
            int nH = (t + 1) * HN_DIM + h * 128;
            int nKV = (t + 1) * KVN_DIM + kvh * 128;
            pw = wdec[nH + tid];
            pb = bb[nH + tid];
            pr = rr[nH + tid];
            pk = kk[nKV + tid];
            pkf = kf[nKV + tid];
            if (tid < 16) pv = vf[nKV + rg * 16 + tid];
        }

        // sa_i = -(sum_j S[i,j] * kk[j])
        float sa = 0.0f;
#pragma unroll
        for (int q = 0; q < 4; q++) {
            float4 a4 = *(const float4*)&sk[j0 + q * 4];
            sa = fmaf(S[q * 4 + 0], a4.x, sa);
            sa = fmaf(S[q * 4 + 1], a4.y, sa);
            sa = fmaf(S[q * 4 + 2], a4.z, sa);
            sa = fmaf(S[q * 4 + 3], a4.w, sa);
        }
        sa += __shfl_xor_sync(0xffffffffu, sa, 1);
        sa += __shfl_xor_sync(0xffffffffu, sa, 2);
        sa += __shfl_xor_sync(0xffffffffu, sa, 4);
        sa = -sa;

        const float v = sv[rl];
        float yp = 0.0f;
#pragma unroll
        for (int q = 0; q < 4; q++) {
            float4 w4 = *(const float4*)&sw[j0 + q * 4];
            float4 b4 = *(const float4*)&sb[j0 + q * 4];
            float4 k4 = *(const float4*)&skf[j0 + q * 4];
            float4 r4 = *(const float4*)&sr[j0 + q * 4];
            float s0 = fmaf(S[q * 4 + 0], w4.x, fmaf(sa, b4.x, v * k4.x));
            float s1 = fmaf(S[q * 4 + 1], w4.y, fmaf(sa, b4.y, v * k4.y));
            float s2 = fmaf(S[q * 4 + 2], w4.z, fmaf(sa, b4.z, v * k4.z));
            float s3 = fmaf(S[q * 4 + 3], w4.w, fmaf(sa, b4.w, v * k4.w));
            S[q * 4 + 0] = s0;
            S[q * 4 + 1] = s1;
            S[q * 4 + 2] = s2;
            S[q * 4 + 3] = s3;
            yp = fmaf(s0, r4.x, yp);
            yp = fmaf(s1, r4.y, yp);
            yp = fmaf(s2, r4.z, yp);
            yp = fmaf(s3, r4.w, yp);
        }
        yp += __shfl_xor_sync(0xffffffffu, yp, 1);
        yp += __shfl_xor_sync(0xffffffffu, yp, 2);
        yp += __shfl_xor_sync(0xffffffffu, yp, 4);
        if (jc == 0) y[t * HN_DIM + h * 128 + row] = yp;
        __syncthreads();
    }
}

// ---------------- merge: yg = (y + coef*v) * g ----------------
__global__ void merge_kernel(const float* __restrict__ y, const float* __restrict__ coef,
                             const float* __restrict__ vf, const float* __restrict__ gbuf,
                             float* __restrict__ yg, int n) {
    int i = blockIdx.x * blockDim.x + threadIdx.x;
    if (i < n) {
        int t = i >> 11;
        int hn = i & 2047;
        int h = hn >> 7;
        int nn = hn & 127;
        float val = y[i] + coef[t * H_NUM + h] * vf[t * KVN_DIM + (h >> 2) * 128 + nn];
        yg[i] = val * gbuf[i];
    }
}

// ---------------- launch ----------------
static float* symAddr(const void* sym) {
    void* p = nullptr;
    cudaGetSymbolAddress(&p, sym);
    return (float*)p;
}

extern "C" void kernel_launch(void* const* d_in, const int* in_sizes, int n_in,
                              void* d_out, int out_size) {
    const float* x = (const float*)d_in[0];
    const float* v_first = (const float*)d_in[1];
    const float* k_first = (const float*)d_in[2];
    const float* amask = (const float*)d_in[3];
    const float* cosb = (const float*)d_in[4];
    const float* sinb = (const float*)d_in[5];
    const float* w0 = (const float*)d_in[6];
    const float* w1 = (const float*)d_in[7];
    const float* w2 = (const float*)d_in[8];
    const float* a0 = (const float*)d_in[9];
    const float* a1 = (const float*)d_in[10];
    const float* a2 = (const float*)d_in[11];
    const float* v0 = (const float*)d_in[12];
    const float* v1 = (const float*)d_in[13];
    const float* v2 = (const float*)d_in[14];
    const float* k0 = (const float*)d_in[15];
    const float* k1 = (const float*)d_in[16];
    const float* k2 = (const float*)d_in[17];
    const float* g1 = (const float*)d_in[18];
    const float* g2 = (const float*)d_in[19];
    const float* r_k = (const float*)d_in[20];
    const float* r_norm_w = (const float*)d_in[21];
    const float* k_norm_w = (const float*)d_in[22];
    const float* W_r = (const float*)d_in[23];
    const float* W_k = (const float*)d_in[24];
    const float* W_v = (const float*)d_in[25];
    const float* W_o = (const float*)d_in[26];
    float* out = (float*)d_out;

    float* xm = symAddr(g_xm);
    float* xr = symAddr(g_xr);
    float* xk = symAddr(g_xk);
    float* xv = symAddr(g_xv);
    float* tw = symAddr(g_tw);
    float* ta = symAddr(g_ta);
    float* tv = symAddr(g_tv);
    float* tk = symAddr(g_tk);
    float* tg = symAddr(g_tg);
    float* wfull = symAddr(g_wfull);
    float* afull = symAddr(g_afull);
    float* gfull = symAddr(g_gfull);
    float* vmix = symAddr(g_vmix);
    float* kmix = symAddr(g_kmix);
    float* rrb = symAddr(g_rr);
    float* kf = symAddr(g_kf);
    float* vf = symAddr(g_vf);
    float* kkb = symAddr(g_kk);
    float* wd = symAddr(g_wd);
    float* bbb = symAddr(g_bb);
    float* coef = symAddr(g_coef);
    float* yb = symAddr(g_y);
    float* yg = symAddr(g_yg);

    const int NTC = T_LEN * C_DIM;
    maskmul_kernel<<<(NTC + 255) / 256, 256>>>(x, amask, xm, NTC);

    auto grd = [](int M, int N) { return dim3((unsigned)((N + 127) / 128), (unsigned)(M / 128)); };
    dim3 th(256);

    // stage-1 projections from xm
    sgemm_kernel<<<grd(2048, 2048), th>>>(xm, W_r, xr, 2048, 2048, 2048);
    sgemm_kernel<<<grd(2048, 512), th>>>(xm, W_k, xk, 2048, 512, 2048);
    sgemm_kernel<<<grd(2048, 512), th>>>(xm, W_v, xv, 2048, 512, 2048);
    sgemm_kernel<<<grd(2048, 160), th>>>(xm, w1, tw, 2048, 160, 2048);
    sgemm_kernel<<<grd(2048, 96), th>>>(xm, a1, ta, 2048, 96, 2048);
    sgemm_kernel<<<grd(2048, 64), th>>>(xm, v1, tv, 2048, 64, 2048);
    sgemm_kernel<<<grd(2048, 64), th>>>(xm, k1, tk, 2048, 64, 2048);
    sgemm_kernel<<<grd(2048, 160), th>>>(xm, g1, tg, 2048, 160, 2048);

    // activations on LoRA mids (tanh for w-path, sigmoid for g-path)
    const int NT160 = T_LEN * 160;
    act_kernel<<<(NT160 + 255) / 256, 256>>>(tw, tg, NT160);

    // stage-2 LoRA expansions
    sgemm_kernel<<<grd(2048, 2048), th>>>(tw, w2, wfull, 2048, 2048, 160);
    sgemm_kernel<<<grd(2048, 2048), th>>>(ta, a2, afull, 2048, 2048, 96);
    sgemm_kernel<<<grd(2048, 2048), th>>>(tg, g2, gfull, 2048, 2048, 160);
    sgemm_kernel<<<grd(2048, 512), th>>>(tv, v2, vmix, 2048, 512, 64);
    sgemm_kernel<<<grd(2048, 512), th>>>(tk, k2, kmix, 2048, 512, 64);

    // postprocess
    pp_kv_kernel<<<dim3(T_LEN, KVH_NUM), 128>>>(xk, xv, kmix, vmix, k_first, v_first,
                                                k0, v0, k_norm_w, cosb, sinb,
                                                kf, vf, kkb);
    pp_h_kernel<<<dim3(T_LEN, H_NUM), 128>>>(xr, wfull, afull, w0, a0, kkb, kf,
                                             r_norm_w, cosb, sinb, r_k,
                                             rrb, wd, bbb, coef);

    // sequential scan: 16 heads x 8 row-groups
    scan_kernel<<<dim3(H_NUM, 8), 128>>>(wd, bbb, kkb, kf, rrb, vf, yb);

    // merge bonus + gate
    const int NHN = T_LEN * HN_DIM;
    merge_kernel<<<(NHN + 255) / 256, 256>>>(yb, coef, vf, gfull, yg, NHN);

    // final projection
    sgemm_kernel<<<grd(2048, 2048), th>>>(yg, W_o, out, 2048, 2048, 2048);
}

// round 2
// speedup vs baseline: 1.0001x; 1.0001x over previous
#include <cuda_runtime.h>
#include <cuda_bf16.h>

#define T_LEN 2048
#define C_DIM 2048
#define H_NUM 16
#define N_DIM 128
#define KVH_NUM 4
#define HN_DIM 2048
#define KVN_DIM 512

// ---------------- scratch (static device globals; no runtime alloc) ----------------
__device__ float g_xm[T_LEN * C_DIM];
__device__ float g_xr[T_LEN * HN_DIM];
__device__ float g_xk[T_LEN * KVN_DIM];
__device__ float g_xv[T_LEN * KVN_DIM];
__device__ float g_tw[T_LEN * 160];
__device__ float g_ta[T_LEN * 96];
__device__ float g_tv[T_LEN * 64];
__device__ float g_tk[T_LEN * 64];
__device__ float g_tg[T_LEN * 160];
__device__ float g_wfull[T_LEN * HN_DIM];
__device__ float g_afull[T_LEN * HN_DIM];
__device__ float g_gfull[T_LEN * HN_DIM];
__device__ float g_vmix[T_LEN * KVN_DIM];
__device__ float g_kmix[T_LEN * KVN_DIM];
__device__ float g_rr[T_LEN * HN_DIM];
__device__ float g_kf[T_LEN * KVN_DIM];
__device__ float g_vf[T_LEN * KVN_DIM];
__device__ float g_kk[T_LEN * KVN_DIM];
__device__ float g_wd[T_LEN * HN_DIM];
__device__ float g_bb[T_LEN * HN_DIM];
__device__ float g_coef[T_LEN * H_NUM];
__device__ float g_y[T_LEN * HN_DIM];
__device__ float g_yg[T_LEN * HN_DIM];

// ---------------- helpers ----------------
__device__ __forceinline__ float sigmoidf_(float x) {
    return 1.0f / (1.0f + expf(-x));
}

// block of 128 threads; red must be shared float[4]
__device__ __forceinline__ float blockReduceSum128(float v, float* red) {
#pragma unroll
    for (int m = 16; m > 0; m >>= 1) v += __shfl_xor_sync(0xffffffffu, v, m);
    __syncthreads();  // protect red from any prior use
    if ((threadIdx.x & 31) == 0) red[threadIdx.x >> 5] = v;
    __syncthreads();
    return red[0] + red[1] + red[2] + red[3];
}

// ---------------- elementwise: xm = x * mask ----------------
__global__ void maskmul_kernel(const float* __restrict__ x, const float* __restrict__ mask,
                               float* __restrict__ xm, int n) {
    int i = blockIdx.x * blockDim.x + threadIdx.x;
    if (i < n) xm[i] = x[i] * mask[i >> 11];  // C_DIM = 2048
}

// ---------------- activations on small LoRA mids ----------------
__global__ void act_kernel(float* __restrict__ tw, float* __restrict__ tg, int n) {
    int i = blockIdx.x * blockDim.x + threadIdx.x;
    if (i < n) {
        tw[i] = tanhf(tw[i]);
        tg[i] = sigmoidf_(tg[i]);
    }
}

// ---------------- SGEMM: C[M,N] = A[M,K] @ B[K,N], fp32, row-major ----------------
// Requires: M % 128 == 0, K % 8 == 0, N % 4 == 0 (true for all calls here).
__global__ __launch_bounds__(256) void sgemm_kernel(const float* __restrict__ A,
                                                    const float* __restrict__ B,
                                                    float* __restrict__ C,
                                                    int M, int N, int K) {
    __shared__ float As[8][128];
    __shared__ float Bs[8][128];
    const int tid = threadIdx.x;
    const int bm = blockIdx.y * 128;
    const int bn = blockIdx.x * 128;
    const int tx = tid & 15;
    const int ty = tid >> 4;

    const int arow = tid >> 1;
    const int acol = (tid & 1) * 4;
    const int brow = tid >> 5;
    const int bcol = (tid & 31) * 4;

    float acc[8][8];
#pragma unroll
    for (int i = 0; i < 8; i++)
#pragma unroll
        for (int j = 0; j < 8; j++) acc[i][j] = 0.0f;

    for (int k0 = 0; k0 < K; k0 += 8) {
        float4 av = *(const float4*)(A + (bm + arow) * K + k0 + acol);
        float4 bv;
        int gcol = bn + bcol;
        if (gcol < N)
            bv = *(const float4*)(B + (k0 + brow) * N + gcol);
        else
            bv = make_float4(0.f, 0.f, 0.f, 0.f);

        __syncthreads();  // previous iteration's compute done
        As[acol + 0][arow] = av.x;
        As[acol + 1][arow] = av.y;
        As[acol + 2][arow] = av.z;
        As[acol + 3][arow] = av.w;
        *(float4*)&Bs[brow][bcol] = bv;
        __syncthreads();

#pragma unroll
        for (int kk = 0; kk < 8; kk++) {
            float4 a0v = *(const float4*)&As[kk][ty * 8];
            float4 a1v = *(const float4*)&As[kk][ty * 8 + 4];
            float4 b0v = *(const float4*)&Bs[kk][tx * 8];
            float4 b1v = *(const float4*)&Bs[kk][tx * 8 + 4];
            float a[8] = {a0v.x, a0v.y, a0v.z, a0v.w, a1v.x, a1v.y, a1v.z, a1v.w};
            float b[8] = {b0v.x, b0v.y, b0v.z, b0v.w, b1v.x, b1v.y, b1v.z, b1v.w};
#pragma unroll
            for (int i = 0; i < 8; i++)
#pragma unroll
                for (int j = 0; j < 8; j++) acc[i][j] = fmaf(a[i], b[j], acc[i][j]);
        }
    }

#pragma unroll
    for (int i = 0; i < 8; i++) {
        int r = bm + ty * 8 + i;
#pragma unroll
        for (int j = 0; j < 8; j++) {
            int c = bn + tx * 8 + j;
            if (c < N) C[r * N + c] = acc[i][j];
        }
    }
}

// ---------------- postprocess per (t, kvh): k-norm/rope/mix, v-mix, kk ----------------
__global__ void pp_kv_kernel(const float* __restrict__ xk, const float* __restrict__ xv,
                             const float* __restrict__ kmix, const float* __restrict__ vmix,
                             const float* __restrict__ k_first, const float* __restrict__ v_first,
                             const float* __restrict__ k0, const float* __restrict__ v0,
                             const float* __restrict__ knw, const float* __restrict__ cosb,
                             const float* __restrict__ sinb,
                             float* __restrict__ kf, float* __restrict__ vfout,
                             float* __restrict__ kkout) {
    int t = blockIdx.x, kvh = blockIdx.y, n = threadIdx.x;
    int idx = t * KVN_DIM + kvh * 128 + n;
    __shared__ float shk[128];
    __shared__ float red[4];

    float k = xk[idx];
    float ss = blockReduceSum128(k * k, red);
    float kn = knw[n] * k * rsqrtf(ss * (1.0f / 128.0f) + 1e-6f);
    shk[n] = kn;
    __syncthreads();
    float rh = (n < 64) ? -shk[n + 64] : shk[n - 64];
    float c = cosb[t * 128 + n], s = sinb[t * 128 + n];
    float kr = fmaf(kn, c, rh * s);

    float kfv = kr + (k_first[idx] - kr) * sigmoidf_(k0[kvh * 128 + n] + kmix[idx]);
    float vv = xv[idx];
    float vfv = vv + (v_first[idx] - vv) * sigmoidf_(v0[kvh * 128 + n] + vmix[idx]);

    float nrm2 = blockReduceSum128(kfv * kfv, red);
    float denom = fmaxf(sqrtf(nrm2), 1e-12f);

    kf[idx] = kfv;
    vfout[idx] = vfv;
    kkout[idx] = kfv / denom;
}

// ---------------- postprocess per (t, h): r norm/rope, wdec, bb, bonus coeff ----------------
__global__ void pp_h_kernel(const float* __restrict__ xr, const float* __restrict__ wfull,
                            const float* __restrict__ afull,
                            const float* __restrict__ w0, const float* __restrict__ a0,
                            const float* __restrict__ kkbuf, const float* __restrict__ kfbuf,
                            const float* __restrict__ rnw, const float* __restrict__ cosb,
                            const float* __restrict__ sinb, const float* __restrict__ r_k,
                            float* __restrict__ rout, float* __restrict__ wdout,
                            float* __restrict__ bbout, float* __restrict__ coef) {
    int t = blockIdx.x, h = blockIdx.y, n = threadIdx.x;
    int hn = h * 128 + n;
    int idx = t * HN_DIM + hn;
    __shared__ float shr[128];
    __shared__ float red[4];

    float r = xr[idx];
    float ss = blockReduceSum128(r * r, red);
    float rn = rnw[n] * r * rsqrtf(ss * (1.0f / 128.0f) + 1e-6f);
    shr[n] = rn;
    __syncthreads();
    float rh = (n < 64) ? -shr[n + 64] : shr[n - 64];
    float c = cosb[t * 128 + n], s = sinb[t * 128 + n];
    float rr = fmaf(rn, c, rh * s);
    rout[idx] = rr;

    // w = -softplus(-(w0 + wfull)) - 0.5 ; wdec = exp(-exp(w))
    float z = w0[hn] + wfull[idx];
    float u = -z;
    float sp = fmaxf(u, 0.0f) + log1pf(expf(-fabsf(u)));  // softplus(-z), stable
    float w = -sp - 0.5f;
    wdout[idx] = expf(-expf(w));

    float a = sigmoidf_(a0[hn] + afull[idx]);
    int kvidx = t * KVN_DIM + (h >> 2) * 128 + n;
    bbout[idx] = kkbuf[kvidx] * a;

    float cp = rr * kfbuf[kvidx] * r_k[hn];
    float cs = blockReduceSum128(cp, red);
    if (n == 0) coef[t * H_NUM + h] = cs;
}

// ---------------- the sequential scan ----------------
// grid (H=16, RG=8), 128 threads: 16 rows x 8 j-chunks of 16. Row-independent recurrence.
__global__ __launch_bounds__(128) void scan_kernel(const float* __restrict__ wdec,
                                                   const float* __restrict__ bb,
                                                   const float* __restrict__ kk,
                                                   const float* __restrict__ kf,
                                                   const float* __restrict__ rr,
                                                   const float* __restrict__ vf,
                                                   float* __restrict__ y) {
    const int h = blockIdx.x;
    const int rg = blockIdx.y;
    const int tid = threadIdx.x;
    const int rl = tid >> 3;   // local row 0..15
    const int jc = tid & 7;    // j-chunk 0..7
    const int row = rg * 16 + rl;
    const int kvh = h >> 2;
    const int j0 = jc * 16;

    __shared__ float sw[128], sb[128], sk[128], skf[128], sr[128], sv[16];

    float S[16];
#pragma unroll
    for (int i = 0; i < 16; i++) S[i] = 0.0f;

    // prefetch t = 0
    int bH = h * 128;
    int bKV = kvh * 128;
    float pw = wdec[bH + tid];
    float pb = bb[bH + tid];
    float pr = rr[bH + tid];
    float pk = kk[bKV + tid];
    float pkf = kf[bKV + tid];
    float pv = (tid < 16) ? vf[bKV + rg * 16 + tid] : 0.0f;

    for (int t = 0; t < T_LEN; t++) {
        sw[tid] = pw;
        sb[tid] = pb;
        sr[tid] = pr;
        sk[tid] = pk;
        skf[tid] = pkf;
        if (tid < 16) sv[tid] = pv;
        __syncthreads();

        if (t + 1 < T_LEN) {  // prefetch next step, overlapped with compute
            int nH = (t + 1) * HN_DIM + h * 128;
            int nKV = (t + 1) * KVN_DIM + kvh * 128;
            pw = wdec[nH + tid];
            pb = bb[nH + tid];
            pr = rr[nH + tid];
            pk = kk[nKV + tid];
            pkf = kf[nKV + tid];
            if (tid < 16) pv = vf[nKV + rg * 16 + tid];
        }

        // sa_i = -(sum_j S[i,j] * kk[j])
        float sa = 0.0f;
#pragma unroll
        for (int q = 0; q < 4; q++) {
            float4 a4 = *(const float4*)&sk[j0 + q * 4];
            sa = fmaf(S[q * 4 + 0], a4.x, sa);
            sa = fmaf(S[q * 4 + 1], a4.y, sa);
            sa = fmaf(S[q * 4 + 2], a4.z, sa);
            sa = fmaf(S[q * 4 + 3], a4.w, sa);
        }
        sa += __shfl_xor_sync(0xffffffffu, sa, 1);
        sa += __shfl_xor_sync(0xffffffffu, sa, 2);
        sa += __shfl_xor_sync(0xffffffffu, sa, 4);
        sa = -sa;

        const float v = sv[rl];
        float yp = 0.0f;
#pragma unroll
        for (int q = 0; q < 4; q++) {
            float4 w4 = *(const float4*)&sw[j0 + q * 4];
            float4 b4 = *(const float4*)&sb[j0 + q * 4];
            float4 k4 = *(const float4*)&skf[j0 + q * 4];
            float4 r4 = *(const float4*)&sr[j0 + q * 4];
            float s0 = fmaf(S[q * 4 + 0], w4.x, fmaf(sa, b4.x, v * k4.x));
            float s1 = fmaf(S[q * 4 + 1], w4.y, fmaf(sa, b4.y, v * k4.y));
            float s2 = fmaf(S[q * 4 + 2], w4.z, fmaf(sa, b4.z, v * k4.z));
            float s3 = fmaf(S[q * 4 + 3], w4.w, fmaf(sa, b4.w, v * k4.w));
            S[q * 4 + 0] = s0;
            S[q * 4 + 1] = s1;
            S[q * 4 + 2] = s2;
            S[q * 4 + 3] = s3;
            yp = fmaf(s0, r4.x, yp);
            yp = fmaf(s1, r4.y, yp);
            yp = fmaf(s2, r4.z, yp);
            yp = fmaf(s3, r4.w, yp);
        }
        yp += __shfl_xor_sync(0xffffffffu, yp, 1);
        yp += __shfl_xor_sync(0xffffffffu, yp, 2);
        yp += __shfl_xor_sync(0xffffffffu, yp, 4);
        if (jc == 0) y[t * HN_DIM + h * 128 + row] = yp;
        __syncthreads();
    }
}

// ---------------- merge: yg = (y + coef*v) * g ----------------
__global__ void merge_kernel(const float* __restrict__ y, const float* __restrict__ coef,
                             const float* __restrict__ vf, const float* __restrict__ gbuf,
                             float* __restrict__ yg, int n) {
    int i = blockIdx.x * blockDim.x + threadIdx.x;
    if (i < n) {
        int t = i >> 11;
        int hn = i & 2047;
        int h = hn >> 7;
        int nn = hn & 127;
        float val = y[i] + coef[t * H_NUM + h] * vf[t * KVN_DIM + (h >> 2) * 128 + nn];
        yg[i] = val * gbuf[i];
    }
}

// ---------------- launch ----------------
static float* symAddr(const void* sym) {
    void* p = nullptr;
    cudaGetSymbolAddress(&p, sym);
    return (float*)p;
}

extern "C" void kernel_launch(void* const* d_in, const int* in_sizes, int n_in,
                              void* d_out, int out_size) {
    const float* x = (const float*)d_in[0];
    const float* v_first = (const float*)d_in[1];
    const float* k_first = (const float*)d_in[2];
    const float* amask = (const float*)d_in[3];
    const float* cosb = (const float*)d_in[4];
    const float* sinb = (const float*)d_in[5];
    const float* w0 = (const float*)d_in[6];
    const float* w1 = (const float*)d_in[7];
    const float* w2 = (const float*)d_in[8];
    const float* a0 = (const float*)d_in[9];
    const float* a1 = (const float*)d_in[10];
    const float* a2 = (const float*)d_in[11];
    const float* v0 = (const float*)d_in[12];
    const float* v1 = (const float*)d_in[13];
    const float* v2 = (const float*)d_in[14];
    const float* k0 = (const float*)d_in[15];
    const float* k1 = (const float*)d_in[16];
    const float* k2 = (const float*)d_in[17];
    const float* g1 = (const float*)d_in[18];
    const float* g2 = (const float*)d_in[19];
    const float* r_k = (const float*)d_in[20];
    const float* r_norm_w = (const float*)d_in[21];
    const float* k_norm_w = (const float*)d_in[22];
    const float* W_r = (const float*)d_in[23];
    const float* W_k = (const float*)d_in[24];
    const float* W_v = (const float*)d_in[25];
    const float* W_o = (const float*)d_in[26];
    float* out = (float*)d_out;

    float* xm = symAddr(g_xm);
    float* xr = symAddr(g_xr);
    float* xk = symAddr(g_xk);
    float* xv = symAddr(g_xv);
    float* tw = symAddr(g_tw);
    float* ta = symAddr(g_ta);
    float* tv = symAddr(g_tv);
    float* tk = symAddr(g_tk);
    float* tg = symAddr(g_tg);
    float* wfull = symAddr(g_wfull);
    float* afull = symAddr(g_afull);
    float* gfull = symAddr(g_gfull);
    float* vmix = symAddr(g_vmix);
    float* kmix = symAddr(g_kmix);
    float* rrb = symAddr(g_rr);
    float* kf = symAddr(g_kf);
    float* vf = symAddr(g_vf);
    float* kkb = symAddr(g_kk);
    float* wd = symAddr(g_wd);
    float* bbb = symAddr(g_bb);
    float* coef = symAddr(g_coef);
    float* yb = symAddr(g_y);
    float* yg = symAddr(g_yg);

    const int NTC = T_LEN * C_DIM;
    maskmul_kernel<<<(NTC + 255) / 256, 256>>>(x, amask, xm, NTC);

    auto grd = [](int M, int N) { return dim3((unsigned)((N + 127) / 128), (unsigned)(M / 128)); };
    dim3 th(256);

    // stage-1 projections from xm
    sgemm_kernel<<<grd(2048, 2048), th>>>(xm, W_r, xr, 2048, 2048, 2048);
    sgemm_kernel<<<grd(2048, 512), th>>>(xm, W_k, xk, 2048, 512, 2048);
    sgemm_kernel<<<grd(2048, 512), th>>>(xm, W_v, xv, 2048, 512, 2048);
    sgemm_kernel<<<grd(2048, 160), th>>>(xm, w1, tw, 2048, 160, 2048);
    sgemm_kernel<<<grd(2048, 96), th>>>(xm, a1, ta, 2048, 96, 2048);
    sgemm_kernel<<<grd(2048, 64), th>>>(xm, v1, tv, 2048, 64, 2048);
    sgemm_kernel<<<grd(2048, 64), th>>>(xm, k1, tk, 2048, 64, 2048);
    sgemm_kernel<<<grd(2048, 160), th>>>(xm, g1, tg, 2048, 160, 2048);

    // activations on LoRA mids (tanh for w-path, sigmoid for g-path)
    const int NT160 = T_LEN * 160;
    act_kernel<<<(NT160 + 255) / 256, 256>>>(tw, tg, NT160);

    // stage-2 LoRA expansions
    sgemm_kernel<<<grd(2048, 2048), th>>>(tw, w2, wfull, 2048, 2048, 160);
    sgemm_kernel<<<grd(2048, 2048), th>>>(ta, a2, afull, 2048, 2048, 96);
    sgemm_kernel<<<grd(2048, 2048), th>>>(tg, g2, gfull, 2048, 2048, 160);
    sgemm_kernel<<<grd(2048, 512), th>>>(tv, v2, vmix, 2048, 512, 64);
    sgemm_kernel<<<grd(2048, 512), th>>>(tk, k2, kmix, 2048, 512, 64);

    // postprocess
    pp_kv_kernel<<<dim3(T_LEN, KVH_NUM), 128>>>(xk, xv, kmix, vmix, k_first, v_first,
                                                k0, v0, k_norm_w, cosb, sinb,
                                                kf, vf, kkb);
    pp_h_kernel<<<dim3(T_LEN, H_NUM), 128>>>(xr, wfull, afull, w0, a0, kkb, kf,
                                             r_norm_w, cosb, sinb, r_k,
                                             rrb, wd, bbb, coef);

    // sequential scan: 16 heads x 8 row-groups
    scan_kernel<<<dim3(H_NUM, 8), 128>>>(wd, bbb, kkb, kf, rrb, vf, yb);

    // merge bonus + gate
    const int NHN = T_LEN * HN_DIM;
    merge_kernel<<<(NHN + 255) / 256, 256>>>(yb, coef, vf, gfull, yg, NHN);

    // final projection
    sgemm_kernel<<<grd(2048, 2048), th>>>(yg, W_o, out, 2048, 2048, 2048);
}

// round 3
// speedup vs baseline: 1.8077x; 1.8076x over previous
#include <cuda_runtime.h>
#include <cuda_bf16.h>
#include <cstdint>

#define T_LEN 2048
#define C_DIM 2048
#define H_NUM 16
#define N_DIM 128
#define KVH_NUM 4
#define HN_DIM 2048
#define KVN_DIM 512

// ---------------- scratch (static device globals; no runtime alloc) ----------------
__device__ float g_xm[T_LEN * C_DIM];
__device__ float g_xr[T_LEN * HN_DIM];
__device__ float g_xk[T_LEN * KVN_DIM];
__device__ float g_xv[T_LEN * KVN_DIM];
__device__ float g_tw[T_LEN * 160];
__device__ float g_ta[T_LEN * 96];
__device__ float g_tv[T_LEN * 64];
__device__ float g_tk[T_LEN * 64];
__device__ float g_tg[T_LEN * 160];
__device__ float g_wfull[T_LEN * HN_DIM];
__device__ float g_afull[T_LEN * HN_DIM];
__device__ float g_gfull[T_LEN * HN_DIM];
__device__ float g_vmix[T_LEN * KVN_DIM];
__device__ float g_kmix[T_LEN * KVN_DIM];
__device__ float g_rr[T_LEN * HN_DIM];
__device__ float g_kf[T_LEN * KVN_DIM];
__device__ float g_vf[T_LEN * KVN_DIM];
__device__ float g_kk[T_LEN * KVN_DIM];
__device__ float g_wd[T_LEN * HN_DIM];
__device__ float g_bb[T_LEN * HN_DIM];
__device__ float g_coef[T_LEN * H_NUM];
__device__ float g_y[T_LEN * HN_DIM];
__device__ float g_yg[T_LEN * HN_DIM];

// bf16 split buffers (K-tripled layouts)
__device__ __nv_bfloat16 g_Ap[(size_t)2048 * 3 * 2048];  // A' = [hi | lo | hi], M x 3K
__device__ __nv_bfloat16 g_Bp[(size_t)3 * 2048 * 2048];  // B' = [hi ; hi ; lo], 3K x N

// ---------------- helpers ----------------
__device__ __forceinline__ float sigmoidf_(float x) {
    return 1.0f / (1.0f + expf(-x));
}

__device__ __forceinline__ float blockReduceSum128(float v, float* red) {
#pragma unroll
    for (int m = 16; m > 0; m >>= 1) v += __shfl_xor_sync(0xffffffffu, v, m);
    __syncthreads();
    if ((threadIdx.x & 31) == 0) red[threadIdx.x >> 5] = v;
    __syncthreads();
    return red[0] + red[1] + red[2] + red[3];
}

// ---------------- elementwise: xm = x * mask ----------------
__global__ void maskmul_kernel(const float* __restrict__ x, const float* __restrict__ mask,
                               float* __restrict__ xm, int n) {
    int i = blockIdx.x * blockDim.x + threadIdx.x;
    if (i < n) xm[i] = x[i] * mask[i >> 11];
}

// ---------------- activations on small LoRA mids ----------------
__global__ void act_kernel(float* __restrict__ tw, float* __restrict__ tg, int n) {
    int i = blockIdx.x * blockDim.x + threadIdx.x;
    if (i < n) {
        tw[i] = tanhf(tw[i]);
        tg[i] = sigmoidf_(tg[i]);
    }
}

// ---------------- split conversions ----------------
// A[M,K] fp32 -> Ap[M,3K] bf16: [hi | lo | hi]
__global__ void splitA_kernel(const float* __restrict__ A, __nv_bfloat16* __restrict__ Ap,
                              int K, int n) {
    int i = blockIdx.x * blockDim.x + threadIdx.x;
    if (i >= n) return;
    int r = i / K, c = i - r * K;
    float x = A[i];
    __nv_bfloat16 hi = __float2bfloat16(x);
    __nv_bfloat16 lo = __float2bfloat16(x - __bfloat162float(hi));
    size_t base = (size_t)r * (3 * K) + c;
    Ap[base] = hi;
    Ap[base + K] = lo;
    Ap[base + 2 * K] = hi;
}

// B[K,N] fp32 -> Bp[3K,N] bf16: [hi ; hi ; lo]
__global__ void splitB_kernel(const float* __restrict__ B, __nv_bfloat16* __restrict__ Bp,
                              int total) {
    int i = blockIdx.x * blockDim.x + threadIdx.x;
    if (i >= total) return;
    float x = B[i];
    __nv_bfloat16 hi = __float2bfloat16(x);
    __nv_bfloat16 lo = __float2bfloat16(x - __bfloat162float(hi));
    Bp[i] = hi;
    Bp[(size_t)total + i] = hi;
    Bp[(size_t)2 * total + i] = lo;
}

// ---------------- bf16 tensor-core GEMM ----------------
// C[M,N] fp32 = A'[M,K3] bf16 @ B'[K3,N] bf16 ; fp32 accumulate.
// Requires M % 128 == 0, K3 % 32 == 0. N arbitrary (even).
#define LDA_S 40
#define LDB_S 136

__global__ __launch_bounds__(256) void bf16_gemm_kernel(
    const __nv_bfloat16* __restrict__ A, const __nv_bfloat16* __restrict__ B,
    float* __restrict__ C, int M, int N, int K3) {
    __shared__ __align__(16) __nv_bfloat16 As[2][128 * LDA_S];
    __shared__ __align__(16) __nv_bfloat16 Bs[2][32 * LDB_S];

    const int tid = threadIdx.x;
    const int bm = blockIdx.y * 128;
    const int bn = blockIdx.x * 128;
    const int warp = tid >> 5;
    const int lane = tid & 31;
    const int wm = warp & 3;   // row block 32*wm
    const int wn = warp >> 2;  // col block 64*wn

    // global->smem mapping
    const int ar = tid >> 2;         // A: row within tile (+64 per iter)
    const int ac = (tid & 3) * 8;    // A: col (8 bf16 = 16B)
    const int br = tid >> 4;         // B: row (+16 per iter)
    const int bc = (tid & 15) * 8;   // B: col
    const int bsz = ((bn + bc) < N) ? 16 : 0;

    float c[2][8][4];
#pragma unroll
    for (int mi = 0; mi < 2; mi++)
#pragma unroll
        for (int ni = 0; ni < 8; ni++)
#pragma unroll
            for (int q = 0; q < 4; q++) c[mi][ni][q] = 0.0f;

    const int KT = K3 >> 5;

    auto load_stage = [&](int st, int kt) {
        int k0 = kt * 32;
#pragma unroll
        for (int it = 0; it < 2; it++) {
            const __nv_bfloat16* src = A + (size_t)(bm + ar + it * 64) * K3 + k0 + ac;
            uint32_t dst = (uint32_t)__cvta_generic_to_shared(&As[st][(ar + it * 64) * LDA_S + ac]);
            asm volatile("cp.async.ca.shared.global [%0], [%1], 16;\n" ::"r"(dst), "l"(src));
        }
#pragma unroll
        for (int it = 0; it < 2; it++) {
            const __nv_bfloat16* src = B + (size_t)(k0 + br + it * 16) * N + bn + bc;
            uint32_t dst = (uint32_t)__cvta_generic_to_shared(&Bs[st][(br + it * 16) * LDB_S + bc]);
            asm volatile("cp.async.ca.shared.global [%0], [%1], 16, %2;\n" ::"r"(dst), "l"(src),
                         "r"(bsz));
        }
        asm volatile("cp.async.commit_group;\n");
    };

    auto compute_stage = [&](int st) {
#pragma unroll
        for (int kk = 0; kk < 32; kk += 16) {
            uint32_t af[2][4];
#pragma unroll
            for (int mi = 0; mi < 2; mi++) {
                uint32_t addr = (uint32_t)__cvta_generic_to_shared(
                    &As[st][(wm * 32 + mi * 16 + (lane & 15)) * LDA_S + kk + (lane >> 4) * 8]);
                asm volatile("ldmatrix.sync.aligned.m8n8.x4.shared.b16 {%0,%1,%2,%3}, [%4];\n"
                             : "=r"(af[mi][0]), "=r"(af[mi][1]), "=r"(af[mi][2]), "=r"(af[mi][3])
                             : "r"(addr));
            }
            uint32_t bfr[8][2];
#pragma unroll
            for (int p = 0; p < 4; p++) {
                uint32_t addr = (uint32_t)__cvta_generic_to_shared(
                    &Bs[st][(kk + (lane & 15)) * LDB_S + wn * 64 + p * 16 + (lane >> 4) * 8]);
                uint32_t b0, b1, b2, b3;
                asm volatile("ldmatrix.sync.aligned.m8n8.x4.trans.shared.b16 {%0,%1,%2,%3}, [%4];\n"
                             : "=r"(b0), "=r"(b1), "=r"(b2), "=r"(b3)
                             : "r"(addr));
                bfr[p * 2][0] = b0;
                bfr[p * 2][1] = b1;
                bfr[p * 2 + 1][0] = b2;
                bfr[p * 2 + 1][1] = b3;
            }
#pragma unroll
            for (int mi = 0; mi < 2; mi++)
#pragma unroll
                for (int ni = 0; ni < 8; ni++) {
                    asm volatile(
                        "mma.sync.aligned.m16n8k16.row.col.f32.bf16.bf16.f32 "
                        "{%0,%1,%2,%3}, {%4,%5,%6,%7}, {%8,%9}, {%0,%1,%2,%3};\n"
                        : "+f"(c[mi][ni][0]), "+f"(c[mi][ni][1]), "+f"(c[mi][ni][2]),
                          "+f"(c[mi][ni][3])
                        : "r"(af[mi][0]), "r"(af[mi][1]), "r"(af[mi][2]), "r"(af[mi][3]),
                          "r"(bfr[ni][0]), "r"(bfr[ni][1]));
                }
        }
    };

    load_stage(0, 0);
    for (int kt = 0; kt < KT; kt++) {
        int st = kt & 1;
        if (kt + 1 < KT) {
            load_stage(st ^ 1, kt + 1);
            asm volatile("cp.async.wait_group 1;\n");
        } else {
            asm volatile("cp.async.wait_group 0;\n");
        }
        __syncthreads();
        compute_stage(st);
        __syncthreads();
    }

#pragma unroll
    for (int mi = 0; mi < 2; mi++) {
        int row = bm + wm * 32 + mi * 16 + (lane >> 2);
#pragma unroll
        for (int ni = 0; ni < 8; ni++) {
            int col = bn + wn * 64 + ni * 8 + (lane & 3) * 2;
            if (col < N) {
                C[(size_t)row * N + col] = c[mi][ni][0];
                C[(size_t)row * N + col + 1] = c[mi][ni][1];
                C[(size_t)(row + 8) * N + col] = c[mi][ni][2];
                C[(size_t)(row + 8) * N + col + 1] = c[mi][ni][3];
            }
        }
    }
}

// ---------------- postprocess per (t, kvh) ----------------
__global__ void pp_kv_kernel(const float* __restrict__ xk, const float* __restrict__ xv,
                             const float* __restrict__ kmix, const float* __restrict__ vmix,
                             const float* __restrict__ k_first, const float* __restrict__ v_first,
                             const float* __restrict__ k0, const float* __restrict__ v0,
                             const float* __restrict__ knw, const float* __restrict__ cosb,
                             const float* __restrict__ sinb,
                             float* __restrict__ kf, float* __restrict__ vfout,
                             float* __restrict__ kkout) {
    int t = blockIdx.x, kvh = blockIdx.y, n = threadIdx.x;
    int idx = t * KVN_DIM + kvh * 128 + n;
    __shared__ float shk[128];
    __shared__ float red[4];

    float k = xk[idx];
    float ss = blockReduceSum128(k * k, red);
    float kn = knw[n] * k * rsqrtf(ss * (1.0f / 128.0f) + 1e-6f);
    shk[n] = kn;
    __syncthreads();
    float rh = (n < 64) ? -shk[n + 64] : shk[n - 64];
    float c = cosb[t * 128 + n], s = sinb[t * 128 + n];
    float kr = fmaf(kn, c, rh * s);

    float kfv = kr + (k_first[idx] - kr) * sigmoidf_(k0[kvh * 128 + n] + kmix[idx]);
    float vv = xv[idx];
    float vfv = vv + (v_first[idx] - vv) * sigmoidf_(v0[kvh * 128 + n] + vmix[idx]);

    float nrm2 = blockReduceSum128(kfv * kfv, red);
    float denom = fmaxf(sqrtf(nrm2), 1e-12f);

    kf[idx] = kfv;
    vfout[idx] = vfv;
    kkout[idx] = kfv / denom;
}

// ---------------- postprocess per (t, h) ----------------
__global__ void pp_h_kernel(const float* __restrict__ xr, const float* __restrict__ wfull,
                            const float* __restrict__ afull,
                            const float* __restrict__ w0, const float* __restrict__ a0,
                            const float* __restrict__ kkbuf, const float* __restrict__ kfbuf,
                            const float* __restrict__ rnw, const float* __restrict__ cosb,
                            const float* __restrict__ sinb, const float* __restrict__ r_k,
                            float* __restrict__ rout, float* __restrict__ wdout,
                            float* __restrict__ bbout, float* __restrict__ coef) {
    int t = blockIdx.x, h = blockIdx.y, n = threadIdx.x;
    int hn = h * 128 + n;
    int idx = t * HN_DIM + hn;
    __shared__ float shr[128];
    __shared__ float red[4];

    float r = xr[idx];
    float ss = blockReduceSum128(r * r, red);
    float rn = rnw[n] * r * rsqrtf(ss * (1.0f / 128.0f) + 1e-6f);
    shr[n] = rn;
    __syncthreads();
    float rh = (n < 64) ? -shr[n + 64] : shr[n - 64];
    float c = cosb[t * 128 + n], s = sinb[t * 128 + n];
    float rr = fmaf(rn, c, rh * s);
    rout[idx] = rr;

    float z = w0[hn] + wfull[idx];
    float u = -z;
    float sp = fmaxf(u, 0.0f) + log1pf(expf(-fabsf(u)));
    float w = -sp - 0.5f;
    wdout[idx] = expf(-expf(w));

    float a = sigmoidf_(a0[hn] + afull[idx]);
    int kvidx = t * KVN_DIM + (h >> 2) * 128 + n;
    bbout[idx] = kkbuf[kvidx] * a;

    float cp = rr * kfbuf[kvidx] * r_k[hn];
    float cs = blockReduceSum128(cp, red);
    if (n == 0) coef[t * H_NUM + h] = cs;
}

// ---------------- the sequential scan ----------------
__global__ __launch_bounds__(128) void scan_kernel(const float* __restrict__ wdec,
                                                   const float* __restrict__ bb,
                                                   const float* __restrict__ kk,
                                                   const float* __restrict__ kf,
                                                   const float* __restrict__ rr,
                                                   const float* __restrict__ vf,
                                                   float* __restrict__ y) {
    const int h = blockIdx.x;
    const int rg = blockIdx.y;
    const int tid = threadIdx.x;
    const int rl = tid >> 3;
    const int jc = tid & 7;
    const int row = rg * 16 + rl;
    const int kvh = h >> 2;
    const int j0 = jc * 16;

    __shared__ float sw[128], sb[128], sk[128], skf[128], sr[128], sv[16];

    float S[16];
#pragma unroll
    for (int i = 0; i < 16; i++) S[i] = 0.0f;

    int bH = h * 128;
    int bKV = kvh * 128;
    float pw = wdec[bH + tid];
    float pb = bb[bH + tid];
    float pr = rr[bH + tid];
    float pk = kk[bKV + tid];
    float pkf = kf[bKV + tid];
    float pv = (tid < 16) ? vf[bKV + rg * 16 + tid] : 0.0f;

    for (int t = 0; t < T_LEN; t++) {
        sw[tid] = pw;
        sb[tid] = pb;
        sr[tid] = pr;
        sk[tid] = pk;
        skf[tid] = pkf;
        if (tid < 16) sv[tid] = pv;
        __syncthreads();

        if (t + 1 < T_LEN) {
            int nH = (t + 1) * HN_DIM + h * 128;
            int nKV = (t + 1) * KVN_DIM + kvh * 128;
            pw = wdec[nH + tid];
            pb = bb[nH + tid];
            pr = rr[nH + tid];
            pk = kk[nKV + tid];
            pkf = kf[nKV + tid];
            if (tid < 16) pv = vf[nKV + rg * 16 + tid];
        }

        float sa = 0.0f;
#pragma unroll
        for (int q = 0; q < 4; q++) {
            float4 a4 = *(const float4*)&sk[j0 + q * 4];
            sa = fmaf(S[q * 4 + 0], a4.x, sa);
            sa = fmaf(S[q * 4 + 1], a4.y, sa);
            sa = fmaf(S[q * 4 + 2], a4.z, sa);
            sa = fmaf(S[q * 4 + 3], a4.w, sa);
        }
        sa += __shfl_xor_sync(0xffffffffu, sa, 1);
        sa += __shfl_xor_sync(0xffffffffu, sa, 2);
        sa += __shfl_xor_sync(0xffffffffu, sa, 4);
        sa = -sa;

        const float v = sv[rl];
        float yp = 0.0f;
#pragma unroll
        for (int q = 0; q < 4; q++) {
            float4 w4 = *(const float4*)&sw[j0 + q * 4];
            float4 b4 = *(const float4*)&sb[j0 + q * 4];
            float4 k4 = *(const float4*)&skf[j0 + q * 4];
            float4 r4 = *(const float4*)&sr[j0 + q * 4];
            float s0 = fmaf(S[q * 4 + 0], w4.x, fmaf(sa, b4.x, v * k4.x));
            float s1 = fmaf(S[q * 4 + 1], w4.y, fmaf(sa, b4.y, v * k4.y));
            float s2 = fmaf(S[q * 4 + 2], w4.z, fmaf(sa, b4.z, v * k4.z));
            float s3 = fmaf(S[q * 4 + 3], w4.w, fmaf(sa, b4.w, v * k4.w));
            S[q * 4 + 0] = s0;
            S[q * 4 + 1] = s1;
            S[q * 4 + 2] = s2;
            S[q * 4 + 3] = s3;
            yp = fmaf(s0, r4.x, yp);
            yp = fmaf(s1, r4.y, yp);
            yp = fmaf(s2, r4.z, yp);
            yp = fmaf(s3, r4.w, yp);
        }
        yp += __shfl_xor_sync(0xffffffffu, yp, 1);
        yp += __shfl_xor_sync(0xffffffffu, yp, 2);
        yp += __shfl_xor_sync(0xffffffffu, yp, 4);
        if (jc == 0) y[t * HN_DIM + h * 128 + row] = yp;
        __syncthreads();
    }
}

// ---------------- merge: yg = (y + coef*v) * g ----------------
__global__ void merge_kernel(const float* __restrict__ y, const float* __restrict__ coef,
                             const float* __restrict__ vf, const float* __restrict__ gbuf,
                             float* __restrict__ yg, int n) {
    int i = blockIdx.x * blockDim.x + threadIdx.x;
    if (i < n) {
        int t = i >> 11;
        int hn = i & 2047;
        int h = hn >> 7;
        int nn = hn & 127;
        float val = y[i] + coef[t * H_NUM + h] * vf[t * KVN_DIM + (h >> 2) * 128 + nn];
        yg[i] = val * gbuf[i];
    }
}

// ---------------- launch ----------------
static float* symAddrF(const void* sym) {
    void* p = nullptr;
    cudaGetSymbolAddress(&p, sym);
    return (float*)p;
}
static __nv_bfloat16* symAddrB(const void* sym) {
    void* p = nullptr;
    cudaGetSymbolAddress(&p, sym);
    return (__nv_bfloat16*)p;
}

extern "C" void kernel_launch(void* const* d_in, const int* in_sizes, int n_in,
                              void* d_out, int out_size) {
    const float* x = (const float*)d_in[0];
    const float* v_first = (const float*)d_in[1];
    const float* k_first = (const float*)d_in[2];
    const float* amask = (const float*)d_in[3];
    const float* cosb = (const float*)d_in[4];
    const float* sinb = (const float*)d_in[5];
    const float* w0 = (const float*)d_in[6];
    const float* w1 = (const float*)d_in[7];
    const float* w2 = (const float*)d_in[8];
    const float* a0 = (const float*)d_in[9];
    const float* a1 = (const float*)d_in[10];
    const float* a2 = (const float*)d_in[11];
    const float* v0 = (const float*)d_in[12];
    const float* v1 = (const float*)d_in[13];
    const float* v2 = (const float*)d_in[14];
    const float* k0 = (const float*)d_in[15];
    const float* k1 = (const float*)d_in[16];
    const float* k2 = (const float*)d_in[17];
    const float* g1 = (const float*)d_in[18];
    const float* g2 = (const float*)d_in[19];
    const float* r_k = (const float*)d_in[20];
    const float* r_norm_w = (const float*)d_in[21];
    const float* k_norm_w = (const float*)d_in[22];
    const float* W_r = (const float*)d_in[23];
    const float* W_k = (const float*)d_in[24];
    const float* W_v = (const float*)d_in[25];
    const float* W_o = (const float*)d_in[26];
    float* out = (float*)d_out;

    float* xm = symAddrF(g_xm);
    float* xr = symAddrF(g_xr);
    float* xk = symAddrF(g_xk);
    float* xv = symAddrF(g_xv);
    float* tw = symAddrF(g_tw);
    float* ta = symAddrF(g_ta);
    float* tv = symAddrF(g_tv);
    float* tk = symAddrF(g_tk);
    float* tg = symAddrF(g_tg);
    float* wfull = symAddrF(g_wfull);
    float* afull = symAddrF(g_afull);
    float* gfull = symAddrF(g_gfull);
    float* vmix = symAddrF(g_vmix);
    float* kmix = symAddrF(g_kmix);
    float* rrb = symAddrF(g_rr);
    float* kf = symAddrF(g_kf);
    float* vf = symAddrF(g_vf);
    float* kkb = symAddrF(g_kk);
    float* wd = symAddrF(g_wd);
    float* bbb = symAddrF(g_bb);
    float* coef = symAddrF(g_coef);
    float* yb = symAddrF(g_y);
    float* yg = symAddrF(g_yg);
    __nv_bfloat16* Ap = symAddrB(g_Ap);
    __nv_bfloat16* Bp = symAddrB(g_Bp);

    const int NTC = T_LEN * C_DIM;
    maskmul_kernel<<<(NTC + 255) / 256, 256>>>(x, amask, xm, NTC);

    // Convert an fp32 A [2048, K] into the K-tripled bf16 layout in Ap.
    auto convA = [&](const float* A, int K) {
        int n = 2048 * K;
        splitA_kernel<<<(n + 255) / 256, 256>>>(A, Ap, K, n);
    };
    // Convert an fp32 B [K, N] into the K-tripled bf16 layout in Bp, then GEMM.
    auto gemm = [&](const float* B, float* C, int N, int K) {
        int total = K * N;
        splitB_kernel<<<(total + 255) / 256, 256>>>(B, Bp, total);
        dim3 grid((N + 127) / 128, 2048 / 128);
        bf16_gemm_kernel<<<grid, 256>>>(Ap, Bp, C, 2048, N, 3 * K);
    };

    // stage-1 projections from xm
    convA(xm, 2048);
    gemm(W_r, xr, 2048, 2048);
    gemm(W_k, xk, 512, 2048);
    gemm(W_v, xv, 512, 2048);
    gemm(w1, tw, 160, 2048);
    gemm(a1, ta, 96, 2048);
    gemm(v1, tv, 64, 2048);
    gemm(k1, tk, 64, 2048);
    gemm(g1, tg, 160, 2048);

    // activations on LoRA mids
    const int NT160 = T_LEN * 160;
    act_kernel<<<(NT160 + 255) / 256, 256>>>(tw, tg, NT160);

    // stage-2 LoRA expansions
    convA(tw, 160);
    gemm(w2, wfull, 2048, 160);
    convA(ta, 96);
    gemm(a2, afull, 2048, 96);
    convA(tg, 160);
    gemm(g2, gfull, 2048, 160);
    convA(tv, 64);
    gemm(v2, vmix, 512, 64);
    convA(tk, 64);
    gemm(k2, kmix, 512, 64);

    // postprocess
    pp_kv_kernel<<<dim3(T_LEN, KVH_NUM), 128>>>(xk, xv, kmix, vmix, k_first, v_first,
                                                k0, v0, k_norm_w, cosb, sinb,
                                                kf, vf, kkb);
    pp_h_kernel<<<dim3(T_LEN, H_NUM), 128>>>(xr, wfull, afull, w0, a0, kkb, kf,
                                             r_norm_w, cosb, sinb, r_k,
                                             rrb, wd, bbb, coef);

    // sequential scan
    scan_kernel<<<dim3(H_NUM, 8), 128>>>(wd, bbb, kkb, kf, rrb, vf, yb);

    // merge bonus + gate
    const int NHN = T_LEN * HN_DIM;
    merge_kernel<<<(NHN + 255) / 256, 256>>>(yb, coef, vf, gfull, yg, NHN);

    // final projection
    convA(yg, 2048);
    gemm(W_o, out, 2048, 2048);
}

// round 4
// speedup vs baseline: 2.2739x; 1.2579x over previous
#include <cuda_runtime.h>
#include <cuda_bf16.h>
#include <cstdint>

#define T_LEN 2048
#define C_DIM 2048
#define H_NUM 16
#define N_DIM 128
#define KVH_NUM 4
#define HN_DIM 2048
#define KVN_DIM 512

// fused stage-1 output column offsets
#define OFF_XR 0
#define OFF_XK 2048
#define OFF_XV 2560
#define OFF_TW 3072
#define OFF_TA 3232
#define OFF_TV 3328
#define OFF_TK 3392
#define OFF_TG 3456
#define NCAT 3616
#define NMID 544  // 160+96+64+64+160

// ---------------- scratch (static device globals; no runtime alloc) ----------------
__device__ float g_Ccat[(size_t)T_LEN * NCAT];
__device__ float g_tw[T_LEN * 160];
__device__ float g_ta[T_LEN * 96];
__device__ float g_tv[T_LEN * 64];
__device__ float g_tk[T_LEN * 64];
__device__ float g_tg[T_LEN * 160];
__device__ float g_wfull[T_LEN * HN_DIM];
__device__ float g_afull[T_LEN * HN_DIM];
__device__ float g_gfull[T_LEN * HN_DIM];
__device__ float g_vmix[T_LEN * KVN_DIM];
__device__ float g_kmix[T_LEN * KVN_DIM];
__device__ float g_rr[T_LEN * HN_DIM];
__device__ float g_kf[T_LEN * KVN_DIM];
__device__ float g_vf[T_LEN * KVN_DIM];
__device__ float g_kk[T_LEN * KVN_DIM];
__device__ float g_wd[T_LEN * HN_DIM];
__device__ float g_bb[T_LEN * HN_DIM];
__device__ float g_coef[T_LEN * H_NUM];
__device__ float g_y[T_LEN * HN_DIM];
__device__ float g_yg[T_LEN * HN_DIM];

// bf16 split buffers (K-tripled layouts)
__device__ __nv_bfloat16 g_Ap[(size_t)2048 * 3 * 2048];   // A' = [hi | lo | hi], M x 3K
__device__ __nv_bfloat16 g_Bp[(size_t)3 * 2048 * NCAT];   // B' = [hi ; hi ; lo], 3K x ldB

// ---------------- helpers ----------------
__device__ __forceinline__ float sigmoidf_(float x) {
    return 1.0f / (1.0f + expf(-x));
}

__device__ __forceinline__ float blockReduceSum128(float v, float* red) {
#pragma unroll
    for (int m = 16; m > 0; m >>= 1) v += __shfl_xor_sync(0xffffffffu, v, m);
    __syncthreads();
    if ((threadIdx.x & 31) == 0) red[threadIdx.x >> 5] = v;
    __syncthreads();
    return red[0] + red[1] + red[2] + red[3];
}

// ---------------- split conversions ----------------
// A[M,K] fp32 (optionally masked) -> Ap[M,3K] bf16: [hi | lo | hi]
__global__ void splitA_kernel(const float* __restrict__ A, __nv_bfloat16* __restrict__ Ap,
                              int K, int n) {
    int i = blockIdx.x * blockDim.x + threadIdx.x;
    if (i >= n) return;
    int r = i / K, c = i - r * K;
    float x = A[i];
    __nv_bfloat16 hi = __float2bfloat16(x);
    __nv_bfloat16 lo = __float2bfloat16(x - __bfloat162float(hi));
    size_t base = (size_t)r * (3 * K) + c;
    Ap[base] = hi;
    Ap[base + K] = lo;
    Ap[base + 2 * K] = hi;
}

// x[M,K] * mask[M] -> Ap (fused mask + split; mask indexed by row = i>>11, K=2048)
__global__ void splitAmask_kernel(const float* __restrict__ x, const float* __restrict__ mask,
                                  __nv_bfloat16* __restrict__ Ap, int n) {
    int i = blockIdx.x * blockDim.x + threadIdx.x;
    if (i >= n) return;
    int r = i >> 11, c = i & 2047;
    float v = x[i] * mask[r];
    __nv_bfloat16 hi = __float2bfloat16(v);
    __nv_bfloat16 lo = __float2bfloat16(v - __bfloat162float(hi));
    size_t base = (size_t)r * 6144 + c;
    Ap[base] = hi;
    Ap[base + 2048] = lo;
    Ap[base + 4096] = hi;
}

// B[K,Ncols] fp32 -> Bp[3K, ldB] bf16 at column colOff: [hi ; hi ; lo]
__global__ void splitB_kernel(const float* __restrict__ B, __nv_bfloat16* __restrict__ Bp,
                              int K, int Ncols, int ldB, int colOff, int total) {
    int i = blockIdx.x * blockDim.x + threadIdx.x;
    if (i >= total) return;
    int r = i / Ncols, c = i - r * Ncols;
    float x = B[i];
    __nv_bfloat16 hi = __float2bfloat16(x);
    __nv_bfloat16 lo = __float2bfloat16(x - __bfloat162float(hi));
    size_t base = (size_t)r * ldB + colOff + c;
    Bp[base] = hi;
    Bp[base + (size_t)K * ldB] = hi;
    Bp[base + (size_t)2 * K * ldB] = lo;
}

// ---------------- bf16 tensor-core GEMM, 3-stage cp.async pipeline ----------------
// C[M,N] fp32 = A'[M,K3] @ B'[K3, ldB] (cols [0,N)) ; C has leading dim ldC.
// Requires M % 128 == 0, K3 % 32 == 0.
#define LDA_S 40
#define LDB_S 136
#define NSTAGE 3

__global__ __launch_bounds__(256) void bf16_gemm_kernel(
    const __nv_bfloat16* __restrict__ A, const __nv_bfloat16* __restrict__ B,
    float* __restrict__ C, int M, int N, int K3, int ldB, int ldC) {
    __shared__ __align__(16) __nv_bfloat16 As[NSTAGE][128 * LDA_S];
    __shared__ __align__(16) __nv_bfloat16 Bs[NSTAGE][32 * LDB_S];

    const int tid = threadIdx.x;
    const int bm = blockIdx.y * 128;
    const int bn = blockIdx.x * 128;
    const int warp = tid >> 5;
    const int lane = tid & 31;
    const int wm = warp & 3;
    const int wn = warp >> 2;

    const int ar = tid >> 2;
    const int ac = (tid & 3) * 8;
    const int br = tid >> 4;
    const int bc = (tid & 15) * 8;
    const int bsz = ((bn + bc) < N) ? 16 : 0;

    float c[2][8][4];
#pragma unroll
    for (int mi = 0; mi < 2; mi++)
#pragma unroll
        for (int ni = 0; ni < 8; ni++)
#pragma unroll
            for (int q = 0; q < 4; q++) c[mi][ni][q] = 0.0f;

    const int KT = K3 >> 5;

    auto load_stage = [&](int st, int kt) {
        int k0 = kt * 32;
#pragma unroll
        for (int it = 0; it < 2; it++) {
            const __nv_bfloat16* src = A + (size_t)(bm + ar + it * 64) * K3 + k0 + ac;
            uint32_t dst = (uint32_t)__cvta_generic_to_shared(&As[st][(ar + it * 64) * LDA_S + ac]);
            asm volatile("cp.async.ca.shared.global [%0], [%1], 16;\n" ::"r"(dst), "l"(src));
        }
#pragma unroll
        for (int it = 0; it < 2; it++) {
            const __nv_bfloat16* src = B + (size_t)(k0 + br + it * 16) * ldB + bn + bc;
            uint32_t dst = (uint32_t)__cvta_generic_to_shared(&Bs[st][(br + it * 16) * LDB_S + bc]);
            asm volatile("cp.async.ca.shared.global [%0], [%1], 16, %2;\n" ::"r"(dst), "l"(src),
                         "r"(bsz));
        }
        asm volatile("cp.async.commit_group;\n");
    };

    auto compute_stage = [&](int st) {
#pragma unroll
        for (int kk = 0; kk < 32; kk += 16) {
            uint32_t af[2][4];
#pragma unroll
            for (int mi = 0; mi < 2; mi++) {
                uint32_t addr = (uint32_t)__cvta_generic_to_shared(
                    &As[st][(wm * 32 + mi * 16 + (lane & 15)) * LDA_S + kk + (lane >> 4) * 8]);
                asm volatile("ldmatrix.sync.aligned.m8n8.x4.shared.b16 {%0,%1,%2,%3}, [%4];\n"
                             : "=r"(af[mi][0]), "=r"(af[mi][1]), "=r"(af[mi][2]), "=r"(af[mi][3])
                             : "r"(addr));
            }
            uint32_t bfr[8][2];
#pragma unroll
            for (int p = 0; p < 4; p++) {
                uint32_t addr = (uint32_t)__cvta_generic_to_shared(
                    &Bs[st][(kk + (lane & 15)) * LDB_S + wn * 64 + p * 16 + (lane >> 4) * 8]);
                uint32_t b0, b1, b2, b3;
                asm volatile("ldmatrix.sync.aligned.m8n8.x4.trans.shared.b16 {%0,%1,%2,%3}, [%4];\n"
                             : "=r"(b0), "=r"(b1), "=r"(b2), "=r"(b3)
                             : "r"(addr));
                bfr[p * 2][0] = b0;
                bfr[p * 2][1] = b1;
                bfr[p * 2 + 1][0] = b2;
                bfr[p * 2 + 1][1] = b3;
            }
#pragma unroll
            for (int mi = 0; mi < 2; mi++)
#pragma unroll
                for (int ni = 0; ni < 8; ni++) {
                    asm volatile(
                        "mma.sync.aligned.m16n8k16.row.col.f32.bf16.bf16.f32 "
                        "{%0,%1,%2,%3}, {%4,%5,%6,%7}, {%8,%9}, {%0,%1,%2,%3};\n"
                        : "+f"(c[mi][ni][0]), "+f"(c[mi][ni][1]), "+f"(c[mi][ni][2]),
                          "+f"(c[mi][ni][3])
                        : "r"(af[mi][0]), "r"(af[mi][1]), "r"(af[mi][2]), "r"(af[mi][3]),
                          "r"(bfr[ni][0]), "r"(bfr[ni][1]));
                }
        }
    };

    load_stage(0, 0);
    if (KT > 1) load_stage(1, 1);
    for (int kt = 0; kt < KT; kt++) {
        if (kt + 2 < KT) {
            load_stage((kt + 2) % NSTAGE, kt + 2);
            asm volatile("cp.async.wait_group 2;\n");
        } else if (kt + 1 < KT) {
            asm volatile("cp.async.wait_group 1;\n");
        } else {
            asm volatile("cp.async.wait_group 0;\n");
        }
        __syncthreads();
        compute_stage(kt % NSTAGE);
        __syncthreads();
    }

#pragma unroll
    for (int mi = 0; mi < 2; mi++) {
        int row = bm + wm * 32 + mi * 16 + (lane >> 2);
#pragma unroll
        for (int ni = 0; ni < 8; ni++) {
            int col = bn + wn * 64 + ni * 8 + (lane & 3) * 2;
            if (col < N) {
                C[(size_t)row * ldC + col] = c[mi][ni][0];
                C[(size_t)row * ldC + col + 1] = c[mi][ni][1];
                C[(size_t)(row + 8) * ldC + col] = c[mi][ni][2];
                C[(size_t)(row + 8) * ldC + col + 1] = c[mi][ni][3];
            }
        }
    }
}

// ---------------- act + compaction of LoRA mids from Ccat ----------------
__global__ void act_kernel(const float* __restrict__ Ccat, float* __restrict__ tw,
                           float* __restrict__ ta, float* __restrict__ tv,
                           float* __restrict__ tk, float* __restrict__ tg, int n) {
    int i = blockIdx.x * blockDim.x + threadIdx.x;
    if (i >= n) return;
    int t = i / NMID, c = i - t * NMID;
    float v = Ccat[(size_t)t * NCAT + OFF_TW + c];
    if (c < 160) tw[t * 160 + c] = tanhf(v);
    else if (c < 256) ta[t * 96 + (c - 160)] = v;
    else if (c < 320) tv[t * 64 + (c - 256)] = v;
    else if (c < 384) tk[t * 64 + (c - 320)] = v;
    else tg[t * 160 + (c - 384)] = sigmoidf_(v);
}

// ---------------- postprocess per (t, kvh) ----------------
__global__ void pp_kv_kernel(const float* __restrict__ Ccat,
                             const float* __restrict__ kmix, const float* __restrict__ vmix,
                             const float* __restrict__ k_first, const float* __restrict__ v_first,
                             const float* __restrict__ k0, const float* __restrict__ v0,
                             const float* __restrict__ knw, const float* __restrict__ cosb,
                             const float* __restrict__ sinb,
                             float* __restrict__ kf, float* __restrict__ vfout,
                             float* __restrict__ kkout) {
    int t = blockIdx.x, kvh = blockIdx.y, n = threadIdx.x;
    int idx = t * KVN_DIM + kvh * 128 + n;
    size_t cidx = (size_t)t * NCAT + kvh * 128 + n;
    __shared__ float shk[128];
    __shared__ float red[4];

    float k = Ccat[cidx + OFF_XK];
    float ss = blockReduceSum128(k * k, red);
    float kn = knw[n] * k * rsqrtf(ss * (1.0f / 128.0f) + 1e-6f);
    shk[n] = kn;
    __syncthreads();
    float rh = (n < 64) ? -shk[n + 64] : shk[n - 64];
    float c = cosb[t * 128 + n], s = sinb[t * 128 + n];
    float kr = fmaf(kn, c, rh * s);

    float kfv = kr + (k_first[idx] - kr) * sigmoidf_(k0[kvh * 128 + n] + kmix[idx]);
    float vv = Ccat[cidx + OFF_XV];
    float vfv = vv + (v_first[idx] - vv) * sigmoidf_(v0[kvh * 128 + n] + vmix[idx]);

    float nrm2 = blockReduceSum128(kfv * kfv, red);
    float denom = fmaxf(sqrtf(nrm2), 1e-12f);

    kf[idx] = kfv;
    vfout[idx] = vfv;
    kkout[idx] = kfv / denom;
}

// ---------------- postprocess per (t, h) ----------------
__global__ void pp_h_kernel(const float* __restrict__ Ccat, const float* __restrict__ wfull,
                            const float* __restrict__ afull,
                            const float* __restrict__ w0, const float* __restrict__ a0,
                            const float* __restrict__ kkbuf, const float* __restrict__ kfbuf,
                            const float* __restrict__ rnw, const float* __restrict__ cosb,
                            const float* __restrict__ sinb, const float* __restrict__ r_k,
                            float* __restrict__ rout, float* __restrict__ wdout,
                            float* __restrict__ bbout, float* __restrict__ coef) {
    int t = blockIdx.x, h = blockIdx.y, n = threadIdx.x;
    int hn = h * 128 + n;
    int idx = t * HN_DIM + hn;
    __shared__ float shr[128];
    __shared__ float red[4];

    float r = Ccat[(size_t)t * NCAT + OFF_XR + hn];
    float ss = blockReduceSum128(r * r, red);
    float rn = rnw[n] * r * rsqrtf(ss * (1.0f / 128.0f) + 1e-6f);
    shr[n] = rn;
    __syncthreads();
    float rh = (n < 64) ? -shr[n + 64] : shr[n - 64];
    float c = cosb[t * 128 + n], s = sinb[t * 128 + n];
    float rr = fmaf(rn, c, rh * s);
    rout[idx] = rr;

    float z = w0[hn] + wfull[idx];
    float u = -z;
    float sp = fmaxf(u, 0.0f) + log1pf(expf(-fabsf(u)));
    float w = -sp - 0.5f;
    wdout[idx] = expf(-expf(w));

    float a = sigmoidf_(a0[hn] + afull[idx]);
    int kvidx = t * KVN_DIM + (h >> 2) * 128 + n;
    bbout[idx] = kkbuf[kvidx] * a;

    float cp = rr * kfbuf[kvidx] * r_k[hn];
    float cs = blockReduceSum128(cp, red);
    if (n == 0) coef[t * H_NUM + h] = cs;
}

// ---------------- the sequential scan ----------------
__global__ __launch_bounds__(128) void scan_kernel(const float* __restrict__ wdec,
                                                   const float* __restrict__ bb,
                                                   const float* __restrict__ kk,
                                                   const float* __restrict__ kf,
                                                   const float* __restrict__ rr,
                                                   const float* __restrict__ vf,
                                                   float* __restrict__ y) {
    const int h = blockIdx.x;
    const int rg = blockIdx.y;
    const int tid = threadIdx.x;
    const int rl = tid >> 3;
    const int jc = tid & 7;
    const int row = rg * 16 + rl;
    const int kvh = h >> 2;
    const int j0 = jc * 16;

    __shared__ float sw[128], sb[128], sk[128], skf[128], sr[128], sv[16];

    float S[16];
#pragma unroll
    for (int i = 0; i < 16; i++) S[i] = 0.0f;

    int bH = h * 128;
    int bKV = kvh * 128;
    float pw = wdec[bH + tid];
    float pb = bb[bH + tid];
    float pr = rr[bH + tid];
    float pk = kk[bKV + tid];
    float pkf = kf[bKV + tid];
    float pv = (tid < 16) ? vf[bKV + rg * 16 + tid] : 0.0f;

    for (int t = 0; t < T_LEN; t++) {
        sw[tid] = pw;
        sb[tid] = pb;
        sr[tid] = pr;
        sk[tid] = pk;
        skf[tid] = pkf;
        if (tid < 16) sv[tid] = pv;
        __syncthreads();

        if (t + 1 < T_LEN) {
            int nH = (t + 1) * HN_DIM + h * 128;
            int nKV = (t + 1) * KVN_DIM + kvh * 128;
            pw = wdec[nH + tid];
            pb = bb[nH + tid];
            pr = rr[nH + tid];
            pk = kk[nKV + tid];
            pkf = kf[nKV + tid];
            if (tid < 16) pv = vf[nKV + rg * 16 + tid];
        }

        float sa = 0.0f;
#pragma unroll
        for (int q = 0; q < 4; q++) {
            float4 a4 = *(const float4*)&sk[j0 + q * 4];
            sa = fmaf(S[q * 4 + 0], a4.x, sa);
            sa = fmaf(S[q * 4 + 1], a4.y, sa);
            sa = fmaf(S[q * 4 + 2], a4.z, sa);
            sa = fmaf(S[q * 4 + 3], a4.w, sa);
        }
        sa += __shfl_xor_sync(0xffffffffu, sa, 1);
        sa += __shfl_xor_sync(0xffffffffu, sa, 2);
        sa += __shfl_xor_sync(0xffffffffu, sa, 4);
        sa = -sa;

        const float v = sv[rl];
        float yp = 0.0f;
#pragma unroll
        for (int q = 0; q < 4; q++) {
            float4 w4 = *(const float4*)&sw[j0 + q * 4];
            float4 b4 = *(const float4*)&sb[j0 + q * 4];
            float4 k4 = *(const float4*)&skf[j0 + q * 4];
            float4 r4 = *(const float4*)&sr[j0 + q * 4];
            float s0 = fmaf(S[q * 4 + 0], w4.x, fmaf(sa, b4.x, v * k4.x));
            float s1 = fmaf(S[q * 4 + 1], w4.y, fmaf(sa, b4.y, v * k4.y));
            float s2 = fmaf(S[q * 4 + 2], w4.z, fmaf(sa, b4.z, v * k4.z));
            float s3 = fmaf(S[q * 4 + 3], w4.w, fmaf(sa, b4.w, v * k4.w));
            S[q * 4 + 0] = s0;
            S[q * 4 + 1] = s1;
            S[q * 4 + 2] = s2;
            S[q * 4 + 3] = s3;
            yp = fmaf(s0, r4.x, yp);
            yp = fmaf(s1, r4.y, yp);
            yp = fmaf(s2, r4.z, yp);
            yp = fmaf(s3, r4.w, yp);
        }
        yp += __shfl_xor_sync(0xffffffffu, yp, 1);
        yp += __shfl_xor_sync(0xffffffffu, yp, 2);
        yp += __shfl_xor_sync(0xffffffffu, yp, 4);
        if (jc == 0) y[t * HN_DIM + h * 128 + row] = yp;
        __syncthreads();
    }
}

// ---------------- merge: yg = (y + coef*v) * g ----------------
__global__ void merge_kernel(const float* __restrict__ y, const float* __restrict__ coef,
                             const float* __restrict__ vf, const float* __restrict__ gbuf,
                             float* __restrict__ yg, int n) {
    int i = blockIdx.x * blockDim.x + threadIdx.x;
    if (i < n) {
        int t = i >> 11;
        int hn = i & 2047;
        int h = hn >> 7;
        int nn = hn & 127;
        float val = y[i] + coef[t * H_NUM + h] * vf[t * KVN_DIM + (h >> 2) * 128 + nn];
        yg[i] = val * gbuf[i];
    }
}

// ---------------- launch ----------------
static float* symAddrF(const void* sym) {
    void* p = nullptr;
    cudaGetSymbolAddress(&p, sym);
    return (float*)p;
}
static __nv_bfloat16* symAddrB(const void* sym) {
    void* p = nullptr;
    cudaGetSymbolAddress(&p, sym);
    return (__nv_bfloat16*)p;
}

extern "C" void kernel_launch(void* const* d_in, const int* in_sizes, int n_in,
                              void* d_out, int out_size) {
    const float* x = (const float*)d_in[0];
    const float* v_first = (const float*)d_in[1];
    const float* k_first = (const float*)d_in[2];
    const float* amask = (const float*)d_in[3];
    const float* cosb = (const float*)d_in[4];
    const float* sinb = (const float*)d_in[5];
    const float* w0 = (const float*)d_in[6];
    const float* w1 = (const float*)d_in[7];
    const float* w2 = (const float*)d_in[8];
    const float* a0 = (const float*)d_in[9];
    const float* a1 = (const float*)d_in[10];
    const float* a2 = (const float*)d_in[11];
    const float* v0 = (const float*)d_in[12];
    const float* v1 = (const float*)d_in[13];
    const float* v2 = (const float*)d_in[14];
    const float* k0 = (const float*)d_in[15];
    const float* k1 = (const float*)d_in[16];
    const float* k2 = (const float*)d_in[17];
    const float* g1 = (const float*)d_in[18];
    const float* g2 = (const float*)d_in[19];
    const float* r_k = (const float*)d_in[20];
    const float* r_norm_w = (const float*)d_in[21];
    const float* k_norm_w = (const float*)d_in[22];
    const float* W_r = (const float*)d_in[23];
    const float* W_k = (const float*)d_in[24];
    const float* W_v = (const float*)d_in[25];
    const float* W_o = (const float*)d_in[26];
    float* out = (float*)d_out;

    float* Ccat = symAddrF(g_Ccat);
    float* tw = symAddrF(g_tw);
    float* ta = symAddrF(g_ta);
    float* tv = symAddrF(g_tv);
    float* tk = symAddrF(g_tk);
    float* tg = symAddrF(g_tg);
    float* wfull = symAddrF(g_wfull);
    float* afull = symAddrF(g_afull);
    float* gfull = symAddrF(g_gfull);
    float* vmix = symAddrF(g_vmix);
    float* kmix = symAddrF(g_kmix);
    float* rrb = symAddrF(g_rr);
    float* kf = symAddrF(g_kf);
    float* vf = symAddrF(g_vf);
    float* kkb = symAddrF(g_kk);
    float* wd = symAddrF(g_wd);
    float* bbb = symAddrF(g_bb);
    float* coef = symAddrF(g_coef);
    float* yb = symAddrF(g_y);
    float* yg = symAddrF(g_yg);
    __nv_bfloat16* Ap = symAddrB(g_Ap);
    __nv_bfloat16* Bp = symAddrB(g_Bp);

    // ---- stage 1: fused masked split of x, concat split of all 8 B matrices ----
    const int NTC = T_LEN * C_DIM;
    splitAmask_kernel<<<(NTC + 255) / 256, 256>>>(x, amask, Ap, NTC);

    auto splitBcat = [&](const float* B, int K, int Ncols, int colOff, int ldB) {
        int total = K * Ncols;
        splitB_kernel<<<(total + 255) / 256, 256>>>(B, Bp, K, Ncols, ldB, colOff, total);
    };
    splitBcat(W_r, 2048, 2048, OFF_XR, NCAT);
    splitBcat(W_k, 2048, 512, OFF_XK, NCAT);
    splitBcat(W_v, 2048, 512, OFF_XV, NCAT);
    splitBcat(w1, 2048, 160, OFF_TW, NCAT);
    splitBcat(a1, 2048, 96, OFF_TA, NCAT);
    splitBcat(v1, 2048, 64, OFF_TV, NCAT);
    splitBcat(k1, 2048, 64, OFF_TK, NCAT);
    splitBcat(g1, 2048, 160, OFF_TG, NCAT);

    {
        dim3 grid((NCAT + 127) / 128, 2048 / 128);
        bf16_gemm_kernel<<<grid, 256>>>(Ap, Bp, Ccat, 2048, NCAT, 6144, NCAT, NCAT);
    }

    // ---- activations + compaction of LoRA mids ----
    const int NMIDS = T_LEN * NMID;
    act_kernel<<<(NMIDS + 255) / 256, 256>>>(Ccat, tw, ta, tv, tk, tg, NMIDS);

    // ---- stage 2: LoRA expansions ----
    auto gemm2 = [&](const float* Asrc, int K, const float* B, float* C, int N) {
        int n = 2048 * K;
        splitA_kernel<<<(n + 255) / 256, 256>>>(Asrc, Ap, K, n);
        int total = K * N;
        splitB_kernel<<<(total + 255) / 256, 256>>>(B, Bp, K, N, N, 0, total);
        dim3 grid((N + 127) / 128, 2048 / 128);
        bf16_gemm_kernel<<<grid, 256>>>(Ap, Bp, C, 2048, N, 3 * K, N, N);
    };
    gemm2(tw, 160, w2, wfull, 2048);
    gemm2(ta, 96, a2, afull, 2048);
    gemm2(tg, 160, g2, gfull, 2048);
    gemm2(tv, 64, v2, vmix, 512);
    gemm2(tk, 64, k2, kmix, 512);

    // ---- postprocess ----
    pp_kv_kernel<<<dim3(T_LEN, KVH_NUM), 128>>>(Ccat, kmix, vmix, k_first, v_first,
                                                k0, v0, k_norm_w, cosb, sinb,
                                                kf, vf, kkb);
    pp_h_kernel<<<dim3(T_LEN, H_NUM), 128>>>(Ccat, wfull, afull, w0, a0, kkb, kf,
                                             r_norm_w, cosb, sinb, r_k,
                                             rrb, wd, bbb, coef);

    // ---- sequential scan ----
    scan_kernel<<<dim3(H_NUM, 8), 128>>>(wd, bbb, kkb, kf, rrb, vf, yb);

    // ---- merge bonus + gate ----
    const int NHN = T_LEN * HN_DIM;
    merge_kernel<<<(NHN + 255) / 256, 256>>>(yb, coef, vf, gfull, yg, NHN);

    // ---- final projection ----
    {
        int n = 2048 * 2048;
        splitA_kernel<<<(n + 255) / 256, 256>>>(yg, Ap, 2048, n);
        int total = 2048 * 2048;
        splitB_kernel<<<(total + 255) / 256, 256>>>(W_o, Bp, 2048, 2048, 2048, 0, total);
        dim3 grid(2048 / 128, 2048 / 128);
        bf16_gemm_kernel<<<grid, 256>>>(Ap, Bp, out, 2048, 2048, 6144, 2048, 2048);
    }
}

// round 5
// speedup vs baseline: 2.6828x; 1.1798x over previous
#include <cuda_runtime.h>
#include <cuda_bf16.h>
#include <cstdint>

#define T_LEN 2048
#define C_DIM 2048
#define H_NUM 16
#define N_DIM 128
#define KVH_NUM 4
#define HN_DIM 2048
#define KVN_DIM 512

// fused stage-1 output column offsets
#define OFF_XR 0
#define OFF_XK 2048
#define OFF_XV 2560
#define OFF_TW 3072
#define OFF_TA 3232
#define OFF_TV 3328
#define OFF_TK 3392
#define OFF_TG 3456
#define NCAT 3616
#define NMID 544

// stage-2 A' regions inside g_Ap (element offsets)
#define APW_BASE 0          // K=160 -> stride 480
#define APA_BASE 983040     // K=96  -> stride 288
#define APG_BASE 1572864    // K=160 -> stride 480
#define APV_BASE 2555904    // K=64  -> stride 192
#define APK_BASE 2949120    // K=64  -> stride 192

// ---------------- scratch ----------------
__device__ float g_Ccat[(size_t)T_LEN * NCAT];
__device__ float g_wfull[T_LEN * HN_DIM];
__device__ float g_afull[T_LEN * HN_DIM];
__device__ float g_gfull[T_LEN * HN_DIM];
__device__ float g_vmix[T_LEN * KVN_DIM];
__device__ float g_kmix[T_LEN * KVN_DIM];
__device__ float g_rr[T_LEN * HN_DIM];
__device__ float g_kf[T_LEN * KVN_DIM];
__device__ float g_vf[T_LEN * KVN_DIM];
__device__ float g_kk[T_LEN * KVN_DIM];
__device__ float g_wd[T_LEN * HN_DIM];
__device__ float g_bb[T_LEN * HN_DIM];
__device__ float g_coef[T_LEN * H_NUM];
__device__ float g_y[T_LEN * HN_DIM];

__device__ __nv_bfloat16 g_Ap[(size_t)2048 * 3 * 2048];
__device__ __nv_bfloat16 g_Bp[(size_t)3 * 2048 * NCAT];

// ---------------- helpers ----------------
__device__ __forceinline__ float sigmoidf_(float x) { return 1.0f / (1.0f + expf(-x)); }

__device__ __forceinline__ float blockReduceSum128(float v, float* red) {
#pragma unroll
    for (int m = 16; m > 0; m >>= 1) v += __shfl_xor_sync(0xffffffffu, v, m);
    __syncthreads();
    if ((threadIdx.x & 31) == 0) red[threadIdx.x >> 5] = v;
    __syncthreads();
    return red[0] + red[1] + red[2] + red[3];
}

__device__ __forceinline__ uint32_t packsplit_hi(float a, float b) {
    __nv_bfloat162 h = __floats2bfloat162_rn(a, b);
    return *(uint32_t*)&h;
}
__device__ __forceinline__ uint32_t packsplit_lo(float a, float b, uint32_t hipack) {
    __nv_bfloat162* hp = (__nv_bfloat162*)&hipack;
    float ra = a - __bfloat162float(hp->x);
    float rb = b - __bfloat162float(hp->y);
    __nv_bfloat162 l = __floats2bfloat162_rn(ra, rb);
    return *(uint32_t*)&l;
}

// ---------------- split conversions (x2 vectorized) ----------------
// x[M,2048] * mask[M] -> Ap[M,6144]: [hi | lo | hi]
__global__ void splitAmask_kernel(const float* __restrict__ x, const float* __restrict__ mask,
                                  __nv_bfloat16* __restrict__ Ap, int n2) {
    int i = blockIdx.x * blockDim.x + threadIdx.x;
    if (i >= n2) return;
    int i2 = i * 2;
    int r = i2 >> 11, c = i2 & 2047;
    float2 xv = *(const float2*)&x[i2];
    float m = mask[r];
    float v0 = xv.x * m, v1 = xv.y * m;
    uint32_t hi = packsplit_hi(v0, v1);
    uint32_t lo = packsplit_lo(v0, v1, hi);
    size_t base = (size_t)r * 6144 + c;
    *(uint32_t*)&Ap[base] = hi;
    *(uint32_t*)&Ap[base + 2048] = lo;
    *(uint32_t*)&Ap[base + 4096] = hi;
}

// generic A split: A[M,K] -> Ap[M,3K] at (region base), K even
__global__ void splitA_kernel(const float* __restrict__ A, __nv_bfloat16* __restrict__ Ap,
                              int K, int n2) {
    int i = blockIdx.x * blockDim.x + threadIdx.x;
    if (i >= n2) return;
    int i2 = i * 2;
    int r = i2 / K, c = i2 - r * K;
    float2 xv = *(const float2*)&A[i2];
    uint32_t hi = packsplit_hi(xv.x, xv.y);
    uint32_t lo = packsplit_lo(xv.x, xv.y, hi);
    size_t base = (size_t)r * (3 * K) + c;
    *(uint32_t*)&Ap[base] = hi;
    *(uint32_t*)&Ap[base + K] = lo;
    *(uint32_t*)&Ap[base + 2 * K] = hi;
}

// B[K,Ncols] -> Bp[3K, ldB] at colOff: [hi ; hi ; lo]; Ncols even
__global__ void splitB_kernel(const float* __restrict__ B, __nv_bfloat16* __restrict__ Bp,
                              int K, int Ncols, int ldB, int colOff, int n2) {
    int i = blockIdx.x * blockDim.x + threadIdx.x;
    if (i >= n2) return;
    int i2 = i * 2;
    int r = i2 / Ncols, c = i2 - r * Ncols;
    float2 xv = *(const float2*)&B[i2];
    uint32_t hi = packsplit_hi(xv.x, xv.y);
    uint32_t lo = packsplit_lo(xv.x, xv.y, hi);
    size_t base = (size_t)r * ldB + colOff + c;
    *(uint32_t*)&Bp[base] = hi;
    *(uint32_t*)&Bp[base + (size_t)K * ldB] = hi;
    *(uint32_t*)&Bp[base + (size_t)2 * K * ldB] = lo;
}

// ---------------- fused act + stage-2 A-split from Ccat ----------------
__global__ void splitMids_kernel(const float* __restrict__ Ccat, __nv_bfloat16* __restrict__ Ap,
                                 int n2) {
    int i = blockIdx.x * blockDim.x + threadIdx.x;
    if (i >= n2) return;
    int i2 = i * 2;
    int t = i2 / NMID, c = i2 - t * NMID;
    const float* src = &Ccat[(size_t)t * NCAT + OFF_TW];
    float v0 = src[c], v1 = src[c + 1];
    int K, lc;
    size_t base;
    if (c < 160) {
        v0 = tanhf(v0); v1 = tanhf(v1);
        K = 160; base = APW_BASE; lc = c;
    } else if (c < 256) {
        K = 96; base = APA_BASE; lc = c - 160;
    } else if (c < 320) {
        K = 64; base = APV_BASE; lc = c - 256;
    } else if (c < 384) {
        K = 64; base = APK_BASE; lc = c - 320;
    } else {
        v0 = sigmoidf_(v0); v1 = sigmoidf_(v1);
        K = 160; base = APG_BASE; lc = c - 384;
    }
    uint32_t hi = packsplit_hi(v0, v1);
    uint32_t lo = packsplit_lo(v0, v1, hi);
    size_t off = base + (size_t)t * (3 * K) + lc;
    *(uint32_t*)&Ap[off] = hi;
    *(uint32_t*)&Ap[off + K] = lo;
    *(uint32_t*)&Ap[off + 2 * K] = hi;
}

// ---------------- fused merge + final A-split ----------------
__global__ void mergeSplitA_kernel(const float* __restrict__ y, const float* __restrict__ coef,
                                   const float* __restrict__ vf, const float* __restrict__ gbuf,
                                   __nv_bfloat16* __restrict__ Ap, int n2) {
    int i = blockIdx.x * blockDim.x + threadIdx.x;
    if (i >= n2) return;
    int i2 = i * 2;
    int t = i2 >> 11, hn = i2 & 2047;
    int h = hn >> 7, nn = hn & 127;
    float cf = coef[t * H_NUM + h];
    const float* vp = &vf[t * KVN_DIM + (h >> 2) * 128 + nn];
    float2 yv = *(const float2*)&y[i2];
    float2 gv = *(const float2*)&gbuf[i2];
    float v0 = (yv.x + cf * vp[0]) * gv.x;
    float v1 = (yv.y + cf * vp[1]) * gv.y;
    uint32_t hi = packsplit_hi(v0, v1);
    uint32_t lo = packsplit_lo(v0, v1, hi);
    size_t base = (size_t)t * 6144 + hn;
    *(uint32_t*)&Ap[base] = hi;
    *(uint32_t*)&Ap[base + 2048] = lo;
    *(uint32_t*)&Ap[base + 4096] = hi;
}

// ---------------- bf16 tensor-core GEMM, 3-stage cp.async pipeline ----------------
#define LDA_S 40
#define LDB_S 136
#define NSTAGE 3

__global__ __launch_bounds__(256) void bf16_gemm_kernel(
    const __nv_bfloat16* __restrict__ A, const __nv_bfloat16* __restrict__ B,
    float* __restrict__ C, int M, int N, int K3, int ldB, int ldC) {
    __shared__ __align__(16) __nv_bfloat16 As[NSTAGE][128 * LDA_S];
    __shared__ __align__(16) __nv_bfloat16 Bs[NSTAGE][32 * LDB_S];

    const int tid = threadIdx.x;
    const int bm = blockIdx.y * 128;
    const int bn = blockIdx.x * 128;
    const int warp = tid >> 5;
    const int lane = tid & 31;
    const int wm = warp & 3;
    const int wn = warp >> 2;

    const int ar = tid >> 2;
    const int ac = (tid & 3) * 8;
    const int br = tid >> 4;
    const int bc = (tid & 15) * 8;
    const int bsz = ((bn + bc) < N) ? 16 : 0;

    float c[2][8][4];
#pragma unroll
    for (int mi = 0; mi < 2; mi++)
#pragma unroll
        for (int ni = 0; ni < 8; ni++)
#pragma unroll
            for (int q = 0; q < 4; q++) c[mi][ni][q] = 0.0f;

    const int KT = K3 >> 5;

    auto load_stage = [&](int st, int kt) {
        int k0 = kt * 32;
#pragma unroll
        for (int it = 0; it < 2; it++) {
            const __nv_bfloat16* src = A + (size_t)(bm + ar + it * 64) * K3 + k0 + ac;
            uint32_t dst = (uint32_t)__cvta_generic_to_shared(&As[st][(ar + it * 64) * LDA_S + ac]);
            asm volatile("cp.async.ca.shared.global [%0], [%1], 16;\n" ::"r"(dst), "l"(src));
        }
#pragma unroll
        for (int it = 0; it < 2; it++) {
            const __nv_bfloat16* src = B + (size_t)(k0 + br + it * 16) * ldB + bn + bc;
            uint32_t dst = (uint32_t)__cvta_generic_to_shared(&Bs[st][(br + it * 16) * LDB_S + bc]);
            asm volatile("cp.async.ca.shared.global [%0], [%1], 16, %2;\n" ::"r"(dst), "l"(src),
                         "r"(bsz));
        }
        asm volatile("cp.async.commit_group;\n");
    };

    auto compute_stage = [&](int st) {
#pragma unroll
        for (int kk = 0; kk < 32; kk += 16) {
            uint32_t af[2][4];
#pragma unroll
            for (int mi = 0; mi < 2; mi++) {
                uint32_t addr = (uint32_t)__cvta_generic_to_shared(
                    &As[st][(wm * 32 + mi * 16 + (lane & 15)) * LDA_S + kk + (lane >> 4) * 8]);
                asm volatile("ldmatrix.sync.aligned.m8n8.x4.shared.b16 {%0,%1,%2,%3}, [%4];\n"
                             : "=r"(af[mi][0]), "=r"(af[mi][1]), "=r"(af[mi][2]), "=r"(af[mi][3])
                             : "r"(addr));
            }
            uint32_t bfr[8][2];
#pragma unroll
            for (int p = 0; p < 4; p++) {
                uint32_t addr = (uint32_t)__cvta_generic_to_shared(
                    &Bs[st][(kk + (lane & 15)) * LDB_S + wn * 64 + p * 16 + (lane >> 4) * 8]);
                uint32_t b0, b1, b2, b3;
                asm volatile("ldmatrix.sync.aligned.m8n8.x4.trans.shared.b16 {%0,%1,%2,%3}, [%4];\n"
                             : "=r"(b0), "=r"(b1), "=r"(b2), "=r"(b3)
                             : "r"(addr));
                bfr[p * 2][0] = b0;
                bfr[p * 2][1] = b1;
                bfr[p * 2 + 1][0] = b2;
                bfr[p * 2 + 1][1] = b3;
            }
#pragma unroll
            for (int mi = 0; mi < 2; mi++)
#pragma unroll
                for (int ni = 0; ni < 8; ni++) {
                    asm volatile(
                        "mma.sync.aligned.m16n8k16.row.col.f32.bf16.bf16.f32 "
                        "{%0,%1,%2,%3}, {%4,%5,%6,%7}, {%8,%9}, {%0,%1,%2,%3};\n"
                        : "+f"(c[mi][ni][0]), "+f"(c[mi][ni][1]), "+f"(c[mi][ni][2]),
                          "+f"(c[mi][ni][3])
                        : "r"(af[mi][0]), "r"(af[mi][1]), "r"(af[mi][2]), "r"(af[mi][3]),
                          "r"(bfr[ni][0]), "r"(bfr[ni][1]));
                }
        }
    };

    load_stage(0, 0);
    if (KT > 1) load_stage(1, 1);
    for (int kt = 0; kt < KT; kt++) {
        if (kt + 2 < KT) {
            load_stage((kt + 2) % NSTAGE, kt + 2);
            asm volatile("cp.async.wait_group 2;\n");
        } else if (kt + 1 < KT) {
            asm volatile("cp.async.wait_group 1;\n");
        } else {
            asm volatile("cp.async.wait_group 0;\n");
        }
        __syncthreads();
        compute_stage(kt % NSTAGE);
        __syncthreads();
    }

#pragma unroll
    for (int mi = 0; mi < 2; mi++) {
        int row = bm + wm * 32 + mi * 16 + (lane >> 2);
#pragma unroll
        for (int ni = 0; ni < 8; ni++) {
            int col = bn + wn * 64 + ni * 8 + (lane & 3) * 2;
            if (col < N) {
                C[(size_t)row * ldC + col] = c[mi][ni][0];
                C[(size_t)row * ldC + col + 1] = c[mi][ni][1];
                C[(size_t)(row + 8) * ldC + col] = c[mi][ni][2];
                C[(size_t)(row + 8) * ldC + col + 1] = c[mi][ni][3];
            }
        }
    }
}

// ---------------- postprocess per (t, kvh) ----------------
__global__ void pp_kv_kernel(const float* __restrict__ Ccat,
                             const float* __restrict__ kmix, const float* __restrict__ vmix,
                             const float* __restrict__ k_first, const float* __restrict__ v_first,
                             const float* __restrict__ k0, const float* __restrict__ v0,
                             const float* __restrict__ knw, const float* __restrict__ cosb,
                             const float* __restrict__ sinb,
                             float* __restrict__ kf, float* __restrict__ vfout,
                             float* __restrict__ kkout) {
    int t = blockIdx.x, kvh = blockIdx.y, n = threadIdx.x;
    int idx = t * KVN_DIM + kvh * 128 + n;
    size_t cidx = (size_t)t * NCAT + kvh * 128 + n;
    __shared__ float shk[128];
    __shared__ float red[4];

    float k = Ccat[cidx + OFF_XK];
    float ss = blockReduceSum128(k * k, red);
    float kn = knw[n] * k * rsqrtf(ss * (1.0f / 128.0f) + 1e-6f);
    shk[n] = kn;
    __syncthreads();
    float rh = (n < 64) ? -shk[n + 64] : shk[n - 64];
    float c = cosb[t * 128 + n], s = sinb[t * 128 + n];
    float kr = fmaf(kn, c, rh * s);

    float kfv = kr + (k_first[idx] - kr) * sigmoidf_(k0[kvh * 128 + n] + kmix[idx]);
    float vv = Ccat[cidx + OFF_XV];
    float vfv = vv + (v_first[idx] - vv) * sigmoidf_(v0[kvh * 128 + n] + vmix[idx]);

    float nrm2 = blockReduceSum128(kfv * kfv, red);
    float denom = fmaxf(sqrtf(nrm2), 1e-12f);

    kf[idx] = kfv;
    vfout[idx] = vfv;
    kkout[idx] = kfv / denom;
}

// ---------------- postprocess per (t, h) ----------------
__global__ void pp_h_kernel(const float* __restrict__ Ccat, const float* __restrict__ wfull,
                            const float* __restrict__ afull,
                            const float* __restrict__ w0, const float* __restrict__ a0,
                            const float* __restrict__ kkbuf, const float* __restrict__ kfbuf,
                            const float* __restrict__ rnw, const float* __restrict__ cosb,
                            const float* __restrict__ sinb, const float* __restrict__ r_k,
                            float* __restrict__ rout, float* __restrict__ wdout,
                            float* __restrict__ bbout, float* __restrict__ coef) {
    int t = blockIdx.x, h = blockIdx.y, n = threadIdx.x;
    int hn = h * 128 + n;
    int idx = t * HN_DIM + hn;
    __shared__ float shr[128];
    __shared__ float red[4];

    float r = Ccat[(size_t)t * NCAT + OFF_XR + hn];
    float ss = blockReduceSum128(r * r, red);
    float rn = rnw[n] * r * rsqrtf(ss * (1.0f / 128.0f) + 1e-6f);
    shr[n] = rn;
    __syncthreads();
    float rh = (n < 64) ? -shr[n + 64] : shr[n - 64];
    float c = cosb[t * 128 + n], s = sinb[t * 128 + n];
    float rr = fmaf(rn, c, rh * s);
    rout[idx] = rr;

    float z = w0[hn] + wfull[idx];
    float u = -z;
    float sp = fmaxf(u, 0.0f) + log1pf(expf(-fabsf(u)));
    float w = -sp - 0.5f;
    wdout[idx] = expf(-expf(w));

    float a = sigmoidf_(a0[hn] + afull[idx]);
    int kvidx = t * KVN_DIM + (h >> 2) * 128 + n;
    bbout[idx] = kkbuf[kvidx] * a;

    float cp = rr * kfbuf[kvidx] * r_k[hn];
    float cs = blockReduceSum128(cp, red);
    if (n == 0) coef[t * H_NUM + h] = cs;
}

// ---------------- the sequential scan ----------------
// grid (16, 8), 128 threads: 16 rows x 8 j-chunks of 16.
// Bank-conflict-free padded staging (stride 20 words per 16-float chunk),
// ping-pong buffers -> ONE barrier per step, depth-2 register prefetch.
#define SCAN_LOAD(R, tn)                                                   \
    {                                                                      \
        size_t oH = (size_t)(tn)*HN_DIM + bH;                              \
        size_t oKV = (size_t)(tn)*KVN_DIM + bKV;                           \
        R##0 = wdec[oH];                                                   \
        R##1 = bb[oH];                                                     \
        R##2 = rr[oH];                                                     \
        R##3 = kk[oKV];                                                    \
        R##4 = kf[oKV];                                                    \
        if (tid < 16) R##5 = vf[(size_t)(tn)*KVN_DIM + vIdx];              \
    }

#define SCAN_STORE(R, s)                                                   \
    {                                                                      \
        sw[s][sidx] = R##0;                                                \
        sb[s][sidx] = R##1;                                                \
        sr[s][sidx] = R##2;                                                \
        sk[s][sidx] = R##3;                                                \
        skf[s][sidx] = R##4;                                               \
        if (tid < 16) sv[s][tid] = R##5;                                   \
    }

#define SCAN_COMPUTE(cbuf, tt)                                             \
    {                                                                      \
        float sa = 0.0f;                                                   \
        _Pragma("unroll") for (int q = 0; q < 4; q++) {                    \
            float4 k4 = *(const float4*)&sk[cbuf][jp + q * 4];             \
            sa = fmaf(S[q * 4 + 0], k4.x, sa);                             \
            sa = fmaf(S[q * 4 + 1], k4.y, sa);                             \
            sa = fmaf(S[q * 4 + 2], k4.z, sa);                             \
            sa = fmaf(S[q * 4 + 3], k4.w, sa);                             \
        }                                                                  \
        sa += __shfl_xor_sync(0xffffffffu, sa, 1);                         \
        sa += __shfl_xor_sync(0xffffffffu, sa, 2);                         \
        sa += __shfl_xor_sync(0xffffffffu, sa, 4);                         \
        sa = -sa;                                                          \
        const float v = sv[cbuf][rl];                                      \
        float yp = 0.0f;                                                   \
        _Pragma("unroll") for (int q = 0; q < 4; q++) {                    \
            float4 w4 = *(const float4*)&sw[cbuf][jp + q * 4];             \
            float4 b4 = *(const float4*)&sb[cbuf][jp + q * 4];             \
            float4 k4 = *(const float4*)&skf[cbuf][jp + q * 4];            \
            float4 r4 = *(const float4*)&sr[cbuf][jp + q * 4];             \
            float s0 = fmaf(S[q * 4 + 0], w4.x, fmaf(sa, b4.x, v * k4.x)); \
            float s1 = fmaf(S[q * 4 + 1], w4.y, fmaf(sa, b4.y, v * k4.y)); \
            float s2 = fmaf(S[q * 4 + 2], w4.z, fmaf(sa, b4.z, v * k4.z)); \
            float s3 = fmaf(S[q * 4 + 3], w4.w, fmaf(sa, b4.w, v * k4.w)); \
            S[q * 4 + 0] = s0;                                             \
            S[q * 4 + 1] = s1;                                             \
            S[q * 4 + 2] = s2;                                             \
            S[q * 4 + 3] = s3;                                             \
            yp = fmaf(s0, r4.x, yp);                                       \
            yp = fmaf(s1, r4.y, yp);                                       \
            yp = fmaf(s2, r4.z, yp);                                       \
            yp = fmaf(s3, r4.w, yp);                                       \
        }                                                                  \
        yp += __shfl_xor_sync(0xffffffffu, yp, 1);                         \
        yp += __shfl_xor_sync(0xffffffffu, yp, 2);                         \
        yp += __shfl_xor_sync(0xffffffffu, yp, 4);                         \
        if (jc == 0) y[(size_t)(tt)*HN_DIM + yIdx] = yp;                   \
    }

__global__ __launch_bounds__(128) void scan_kernel(const float* __restrict__ wdec,
                                                   const float* __restrict__ bb,
                                                   const float* __restrict__ kk,
                                                   const float* __restrict__ kf,
                                                   const float* __restrict__ rr,
                                                   const float* __restrict__ vf,
                                                   float* __restrict__ y) {
    const int h = blockIdx.x;
    const int rg = blockIdx.y;
    const int tid = threadIdx.x;
    const int rl = tid >> 3;
    const int jc = tid & 7;
    const int kvh = h >> 2;
    const int jp = jc * 20;  // padded word offset of this thread's 16-float slice

    __shared__ __align__(16) float sw[2][160], sb[2][160], sk[2][160], skf[2][160], sr[2][160];
    __shared__ float sv[2][16];

    const int sidx = tid + ((tid >> 4) << 2);  // padded store index
    const int bH = h * 128 + tid;
    const int bKV = kvh * 128 + tid;
    const int vIdx = kvh * 128 + rg * 16 + tid;  // only valid for tid<16
    const int yIdx = h * 128 + rg * 16 + rl;

    float S[16];
#pragma unroll
    for (int i = 0; i < 16; i++) S[i] = 0.0f;

    float A0, A1, A2, A3, A4, A5 = 0.0f;
    float B0, B1, B2, B3, B4, B5 = 0.0f;

    SCAN_LOAD(A, 0);
    SCAN_STORE(A, 0);
    SCAN_LOAD(B, 1);
    __syncthreads();

    for (int t = 0; t < T_LEN; t += 2) {
        // substep t: read buf0; stage t+1 (regs B) into buf1; prefetch t+2 -> A
        SCAN_STORE(B, 1);
        {
            int tn = (t + 2 < T_LEN) ? t + 2 : T_LEN - 1;
            SCAN_LOAD(A, tn);
        }
        SCAN_COMPUTE(0, t);
        __syncthreads();

        // substep t+1: read buf1; stage t+2 (regs A) into buf0; prefetch t+3 -> B
        SCAN_STORE(A, 0);
        {
            int tn = (t + 3 < T_LEN) ? t + 3 : T_LEN - 1;
            SCAN_LOAD(B, tn);
        }
        SCAN_COMPUTE(1, t + 1);
        __syncthreads();
    }
}

// ---------------- launch ----------------
static float* symAddrF(const void* sym) {
    void* p = nullptr;
    cudaGetSymbolAddress(&p, sym);
    return (float*)p;
}
static __nv_bfloat16* symAddrB(const void* sym) {
    void* p = nullptr;
    cudaGetSymbolAddress(&p, sym);
    return (__nv_bfloat16*)p;
}

extern "C" void kernel_launch(void* const* d_in, const int* in_sizes, int n_in,
                              void* d_out, int out_size) {
    const float* x = (const float*)d_in[0];
    const float* v_first = (const float*)d_in[1];
    const float* k_first = (const float*)d_in[2];
    const float* amask = (const float*)d_in[3];
    const float* cosb = (const float*)d_in[4];
    const float* sinb = (const float*)d_in[5];
    const float* w0 = (const float*)d_in[6];
    const float* w1 = (const float*)d_in[7];
    const float* w2 = (const float*)d_in[8];
    const float* a0 = (const float*)d_in[9];
    const float* a1 = (const float*)d_in[10];
    const float* a2 = (const float*)d_in[11];
    const float* v0 = (const float*)d_in[12];
    const float* v1 = (const float*)d_in[13];
    const float* v2 = (const float*)d_in[14];
    const float* k0 = (const float*)d_in[15];
    const float* k1 = (const float*)d_in[16];
    const float* k2 = (const float*)d_in[17];
    const float* g1 = (const float*)d_in[18];
    const float* g2 = (const float*)d_in[19];
    const float* r_k = (const float*)d_in[20];
    const float* r_norm_w = (const float*)d_in[21];
    const float* k_norm_w = (const float*)d_in[22];
    const float* W_r = (const float*)d_in[23];
    const float* W_k = (const float*)d_in[24];
    const float* W_v = (const float*)d_in[25];
    const float* W_o = (const float*)d_in[26];
    float* out = (float*)d_out;

    float* Ccat = symAddrF(g_Ccat);
    float* wfull = symAddrF(g_wfull);
    float* afull = symAddrF(g_afull);
    float* gfull = symAddrF(g_gfull);
    float* vmix = symAddrF(g_vmix);
    float* kmix = symAddrF(g_kmix);
    float* rrb = symAddrF(g_rr);
    float* kf = symAddrF(g_kf);
    float* vf = symAddrF(g_vf);
    float* kkb = symAddrF(g_kk);
    float* wd = symAddrF(g_wd);
    float* bbb = symAddrF(g_bb);
    float* coef = symAddrF(g_coef);
    float* yb = symAddrF(g_y);
    __nv_bfloat16* Ap = symAddrB(g_Ap);
    __nv_bfloat16* Bp = symAddrB(g_Bp);

    // ---- stage 1: fused masked split of x; concat split of the 8 B matrices ----
    const int NTC2 = T_LEN * C_DIM / 2;
    splitAmask_kernel<<<(NTC2 + 255) / 256, 256>>>(x, amask, Ap, NTC2);

    auto splitBcat = [&](const float* B, int K, int Ncols, int colOff, int ldB) {
        int n2 = K * Ncols / 2;
        splitB_kernel<<<(n2 + 255) / 256, 256>>>(B, Bp, K, Ncols, ldB, colOff, n2);
    };
    splitBcat(W_r, 2048, 2048, OFF_XR, NCAT);
    splitBcat(W_k, 2048, 512, OFF_XK, NCAT);
    splitBcat(W_v, 2048, 512, OFF_XV, NCAT);
    splitBcat(w1, 2048, 160, OFF_TW, NCAT);
    splitBcat(a1, 2048, 96, OFF_TA, NCAT);
    splitBcat(v1, 2048, 64, OFF_TV, NCAT);
    splitBcat(k1, 2048, 64, OFF_TK, NCAT);
    splitBcat(g1, 2048, 160, OFF_TG, NCAT);

    {
        dim3 grid((NCAT + 127) / 128, 2048 / 128);
        bf16_gemm_kernel<<<grid, 256>>>(Ap, Bp, Ccat, 2048, NCAT, 6144, NCAT, NCAT);
    }

    // ---- fused activations + stage-2 A splits ----
    const int NMIDS2 = T_LEN * NMID / 2;
    splitMids_kernel<<<(NMIDS2 + 255) / 256, 256>>>(Ccat, Ap, NMIDS2);

    // ---- stage 2: LoRA expansions ----
    auto gemm2 = [&](size_t aBase, int K, const float* B, float* C, int N) {
        int n2 = K * N / 2;
        splitB_kernel<<<(n2 + 255) / 256, 256>>>(B, Bp, K, N, N, 0, n2);
        dim3 grid((N + 127) / 128, 2048 / 128);
        bf16_gemm_kernel<<<grid, 256>>>(Ap + aBase, Bp, C, 2048, N, 3 * K, N, N);
    };
    gemm2(APW_BASE, 160, w2, wfull, 2048);
    gemm2(APA_BASE, 96, a2, afull, 2048);
    gemm2(APG_BASE, 160, g2, gfull, 2048);
    gemm2(APV_BASE, 64, v2, vmix, 512);
    gemm2(APK_BASE, 64, k2, kmix, 512);

    // ---- postprocess ----
    pp_kv_kernel<<<dim3(T_LEN, KVH_NUM), 128>>>(Ccat, kmix, vmix, k_first, v_first,
                                                k0, v0, k_norm_w, cosb, sinb,
                                                kf, vf, kkb);
    pp_h_kernel<<<dim3(T_LEN, H_NUM), 128>>>(Ccat, wfull, afull, w0, a0, kkb, kf,
                                             r_norm_w, cosb, sinb, r_k,
                                             rrb, wd, bbb, coef);

    // ---- sequential scan ----
    scan_kernel<<<dim3(H_NUM, 8), 128>>>(wd, bbb, kkb, kf, rrb, vf, yb);

    // ---- fused merge + final A split ----
    const int NHN2 = T_LEN * HN_DIM / 2;
    mergeSplitA_kernel<<<(NHN2 + 255) / 256, 256>>>(yb, coef, vf, gfull, Ap, NHN2);

    // ---- final projection ----
    {
        int n2 = 2048 * 2048 / 2;
        splitB_kernel<<<(n2 + 255) / 256, 256>>>(W_o, Bp, 2048, 2048, 2048, 0, n2);
        dim3 grid(2048 / 128, 2048 / 128);
        bf16_gemm_kernel<<<grid, 256>>>(Ap, Bp, out, 2048, 2048, 6144, 2048, 2048);
    }
}